// round 15
// baseline (speedup 1.0000x reference)
#include <cuda_runtime.h>
#include <cuda_bf16.h>
#include <cstdint>
#include <stdint.h>
#include <math.h>

#define NROWS 131072
#define EDGES 1048576

// ---------------- scratch (device globals) ----------------
__device__ float g_bufA[NROWS * 64];
__device__ float g_bufB[NROWS * 64];
__device__ float g_bufC[NROWS * 64];
__device__ float g_deg[NROWS];      // dinv
__device__ int   g_hist[NROWS];     // zeroed at END of pipeline (fused_final tail)
__device__ int   g_off[NROWS];
__device__ int   g_cursor[NROWS];
__device__ int   g_bsum[128];
__device__ int   g_srcs[EDGES];
__device__ float g_stats[256];      // zeroed early (scan1 tail)
__device__ float g_wbar[65];
// bf16 weight tiles, XOR-swizzled 128B rows, hi tile then lo tile
__device__ __align__(16) __nv_bfloat16 g_wt1[24576];  // tconv l1: [tap*2+split][64x64]
__device__ __align__(16) __nv_bfloat16 g_wt2[24576];  // tconv l2
__device__ __align__(16) __nv_bfloat16 g_gw1[8192];   // gcn1_w [32k x 64n]
__device__ __align__(16) __nv_bfloat16 g_gw2[8192];   // gcn2_w [64k x 64n]
__device__ __align__(16) __nv_bfloat16 g_ow1[8192];   // o1_w^T [64c x 64c2]
__device__ __align__(16) __nv_bfloat16 g_ow2[8192];   // o2_w^T

typedef unsigned long long ull;
__device__ __forceinline__ float tanh_ap(float x) {
    float y; asm("tanh.approx.f32 %0,%1;" : "=f"(y) : "f"(x)); return y;
}

// ---------------- mma.sync helpers ----------------
__device__ __forceinline__ unsigned smem_u32(const void* p) {
    unsigned a;
    asm("{ .reg .u64 t; cvta.to.shared.u64 t, %1; cvt.u32.u64 %0, t; }" : "=r"(a) : "l"(p));
    return a;
}
__device__ __forceinline__ void ldsm4(unsigned& r0, unsigned& r1, unsigned& r2, unsigned& r3,
                                      unsigned addr) {
    asm volatile("ldmatrix.sync.aligned.m8n8.x4.shared.b16 {%0,%1,%2,%3}, [%4];"
                 : "=r"(r0), "=r"(r1), "=r"(r2), "=r"(r3) : "r"(addr));
}
__device__ __forceinline__ void ldsm4t(unsigned& r0, unsigned& r1, unsigned& r2, unsigned& r3,
                                       unsigned addr) {
    asm volatile("ldmatrix.sync.aligned.m8n8.x4.trans.shared.b16 {%0,%1,%2,%3}, [%4];"
                 : "=r"(r0), "=r"(r1), "=r"(r2), "=r"(r3) : "r"(addr));
}
__device__ __forceinline__ void mma_bf16(float* c, unsigned a0, unsigned a1, unsigned a2,
                                         unsigned a3, unsigned b0, unsigned b1) {
    asm volatile(
        "mma.sync.aligned.m16n8k16.row.col.f32.bf16.bf16.f32 "
        "{%0,%1,%2,%3}, {%4,%5,%6,%7}, {%8,%9}, {%0,%1,%2,%3};"
        : "+f"(c[0]), "+f"(c[1]), "+f"(c[2]), "+f"(c[3])
        : "r"(a0), "r"(a1), "r"(a2), "r"(a3), "r"(b0), "r"(b1));
}
__device__ __forceinline__ void split_store(char* hi, char* lo, int sw, float4 v) {
    __nv_bfloat162 h01 = __floats2bfloat162_rn(v.x, v.y);
    __nv_bfloat162 h23 = __floats2bfloat162_rn(v.z, v.w);
    float lx = v.x - __bfloat162float(h01.x);
    float ly = v.y - __bfloat162float(h01.y);
    float lz = v.z - __bfloat162float(h23.x);
    float lw = v.w - __bfloat162float(h23.y);
    __nv_bfloat162 l01 = __floats2bfloat162_rn(lx, ly);
    __nv_bfloat162 l23 = __floats2bfloat162_rn(lz, lw);
    uint2 hp, lp;
    hp.x = *(unsigned*)&h01; hp.y = *(unsigned*)&h23;
    lp.x = *(unsigned*)&l01; lp.y = *(unsigned*)&l23;
    *(uint2*)(hi + sw) = hp;
    *(uint2*)(lo + sw) = lp;
}
__device__ __forceinline__ void split_store1(char* hi, char* lo, int sw, float v) {
    __nv_bfloat16 h = __float2bfloat16_rn(v);
    __nv_bfloat16 l = __float2bfloat16_rn(v - __bfloat162float(h));
    *(__nv_bfloat16*)(hi + sw) = h;
    *(__nv_bfloat16*)(lo + sw) = l;
}

// one k16 step of the 3-term bf16 split GEMM: Ah*Bh + Ah*Bl + Al*Bh
__device__ __forceinline__ void mma_3split_k16(float acc[8][4], unsigned ahRow, unsigned alRow,
                                               unsigned asw, unsigned bhTile, unsigned blTile,
                                               int k16, int arow, int lext) {
    unsigned a0, a1, a2, a3, c0, c1, c2, c3;
    unsigned kb = (((unsigned)(k16 * 32)) + lext) ^ asw;
    ldsm4(a0, a1, a2, a3, ahRow + kb);
    ldsm4(c0, c1, c2, c3, alRow + kb);
    int krow = k16 * 16 + arow;
    unsigned bro = (unsigned)(krow * 128);
    unsigned bsw = (unsigned)((krow & 7) << 4);
    #pragma unroll
    for (int nn = 0; nn < 4; nn++) {
        unsigned b0, b1, b2, b3, d0, d1, d2, d3;
        unsigned nb = (((unsigned)(nn * 32)) + lext) ^ bsw;
        ldsm4t(b0, b1, b2, b3, bhTile + bro + nb);
        ldsm4t(d0, d1, d2, d3, blTile + bro + nb);
        mma_bf16(acc[2 * nn],     a0, a1, a2, a3, b0, b1);
        mma_bf16(acc[2 * nn + 1], a0, a1, a2, a3, b2, b3);
        mma_bf16(acc[2 * nn],     a0, a1, a2, a3, d0, d1);
        mma_bf16(acc[2 * nn + 1], a0, a1, a2, a3, d2, d3);
        mma_bf16(acc[2 * nn],     c0, c1, c2, c3, b0, b1);
        mma_bf16(acc[2 * nn + 1], c0, c1, c2, c3, b2, b3);
    }
}

__device__ __forceinline__ void mma_3split_64(float acc[8][4], unsigned sb, unsigned ahOff,
                                              unsigned alOff, unsigned wOff, int m0, int lane) {
    int arow = lane & 15;
    int lext = (lane >> 4) << 4;
    int ay = m0 + arow;
    unsigned ahRow = sb + ahOff + (unsigned)(ay * 128);
    unsigned alRow = sb + alOff + (unsigned)(ay * 128);
    unsigned asw = (unsigned)((ay & 7) << 4);
    #pragma unroll
    for (int k16 = 0; k16 < 4; k16++)
        mma_3split_k16(acc, ahRow, alRow, asw, sb + wOff, sb + wOff + 8192u, k16, arow, lext);
}

// ---------------- phist: hist atomics + weight prep (merged prologue) ----------------
__global__ void phist_kernel(const int* __restrict__ dst,
                             const float* __restrict__ rw, const float* __restrict__ rb,
                             const float* __restrict__ t1w, const float* __restrict__ t2w,
                             const float* __restrict__ g1w, const float* __restrict__ g2w,
                             const float* __restrict__ o1w, const float* __restrict__ o2w) {
    int i = blockIdx.x * blockDim.x + threadIdx.x;    // 0 .. EDGES-1
    atomicAdd(&g_hist[dst[i]], 1);

    if (i < 12288) {
        int k = i >> 12;
        int r = i & 4095;
        int c2 = r >> 6, c = r & 63;
        int off = c * 128 + c2 * 2;
        int sw = off ^ ((off >> 3) & 0x70);
        int idx = sw >> 1;
        float w1 = t1w[(c2 * 64 + c) * 3 + k];
        float w2 = t2w[(c2 * 64 + c) * 3 + k];
        __nv_bfloat16 h1 = __float2bfloat16_rn(w1);
        __nv_bfloat16 h2 = __float2bfloat16_rn(w2);
        g_wt1[(k * 2 + 0) * 4096 + idx] = h1;
        g_wt1[(k * 2 + 1) * 4096 + idx] = __float2bfloat16_rn(w1 - __bfloat162float(h1));
        g_wt2[(k * 2 + 0) * 4096 + idx] = h2;
        g_wt2[(k * 2 + 1) * 4096 + idx] = __float2bfloat16_rn(w2 - __bfloat162float(h2));
    } else if (i < 16384) {
        int j = i - 12288;
        int k = j >> 6, n = j & 63;
        int off = k * 128 + n * 2;
        int sw = off ^ ((off >> 3) & 0x70);
        int idx = sw >> 1;
        float w = g2w[k * 64 + n];
        __nv_bfloat16 h = __float2bfloat16_rn(w);
        g_gw2[idx] = h;
        g_gw2[4096 + idx] = __float2bfloat16_rn(w - __bfloat162float(h));
    } else if (i < 20480) {
        int j = i - 16384;
        int c = j >> 6, c2 = j & 63;
        int off = c * 128 + c2 * 2;
        int sw = off ^ ((off >> 3) & 0x70);
        int idx = sw >> 1;
        float w = o1w[c2 * 64 + c];
        __nv_bfloat16 h = __float2bfloat16_rn(w);
        g_ow1[idx] = h;
        g_ow1[4096 + idx] = __float2bfloat16_rn(w - __bfloat162float(h));
    } else if (i < 24576) {
        int j = i - 20480;
        int c = j >> 6, c2 = j & 63;
        int off = c * 128 + c2 * 2;
        int sw = off ^ ((off >> 3) & 0x70);
        int idx = sw >> 1;
        float w = o2w[c2 * 64 + c];
        __nv_bfloat16 h = __float2bfloat16_rn(w);
        g_ow2[idx] = h;
        g_ow2[4096 + idx] = __float2bfloat16_rn(w - __bfloat162float(h));
    } else if (i < 26624) {
        int j = i - 24576;
        int k = j >> 6, n = j & 63;
        int off = k * 128 + n * 2;
        int sw = off ^ ((off >> 3) & 0x70);
        int idx = sw >> 1;
        float w = g1w[k * 64 + n];
        __nv_bfloat16 h = __float2bfloat16_rn(w);
        g_gw1[idx] = h;
        g_gw1[4096 + idx] = __float2bfloat16_rn(w - __bfloat162float(h));
    }
    if (i < 64) {
        float s = 0.f;
        #pragma unroll
        for (int j = 0; j < 8; j++) s += rw[i * 8 + j];
        g_wbar[i] = s * 0.125f;
    }
    if (i == 64) {
        float s = 0.f;
        #pragma unroll
        for (int j = 0; j < 8; j++) s += rb[j];
        g_wbar[64] = s * 0.125f;
    }
}

__global__ void scan1_kernel() {
    __shared__ int sh[256];
    int tid = threadIdx.x;
    int base = blockIdx.x * 1024 + tid * 4;
    int4 v = *(const int4*)&g_hist[base];
    int s0 = v.x, s1 = s0 + v.y, s2 = s1 + v.z, s3 = s2 + v.w;
    sh[tid] = s3;
    __syncthreads();
    #pragma unroll
    for (int o = 1; o < 256; o <<= 1) {
        int t = (tid >= o) ? sh[tid - o] : 0;
        __syncthreads();
        sh[tid] += t;
        __syncthreads();
    }
    int excl = tid ? sh[tid - 1] : 0;
    int4 w = make_int4(excl, excl + s0, excl + s1, excl + s2);
    *(int4*)&g_off[base] = w;
    if (tid == 255) g_bsum[blockIdx.x] = sh[255];
    // zero stats for this call (dead since previous call's fused_final)
    int gi = blockIdx.x * 256 + tid;
    if (gi < 256) g_stats[gi] = 0.0f;
}

// scan3: local re-scan of the 128 segment sums + dinv/cursor/out-init
__global__ void scan3_kernel(const float* __restrict__ rb, float* __restrict__ out) {
    __shared__ int bs[128];
    int tid = threadIdx.x;
    if (tid < 128) bs[tid] = g_bsum[tid];
    __syncthreads();
    #pragma unroll
    for (int o = 1; o < 128; o <<= 1) {
        int t = (tid < 128 && tid >= o) ? bs[tid - o] : 0;
        __syncthreads();
        if (tid < 128) bs[tid] += t;
        __syncthreads();
    }
    int i = blockIdx.x * blockDim.x + tid;
    if (i < NROWS) {
        int seg = i >> 10;
        int o = g_off[i] + (seg ? bs[seg - 1] : 0);
        g_off[i] = o;
        g_cursor[i] = o;
        g_deg[i] = rsqrtf((float)g_hist[i] + 1.0f);
    }
    if (i < 1024) {
        float s = 0.f;
        #pragma unroll
        for (int j = 0; j < 8; j++) s += rb[j];
        out[i] = s * 0.125f;
    }
}

__global__ void scatter_kernel(const int* __restrict__ src, const int* __restrict__ dst) {
    int e = blockIdx.x * blockDim.x + threadIdx.x;
    if (e < EDGES) {
        int d = dst[e];
        int pos = atomicAdd(&g_cursor[d], 1);
        g_srcs[pos] = src[e];
    }
}

// ---------------- GEMM hs = (A@W)*dinv via mma.sync (layer 1 input) ----------------
#define GM_AH 0
#define GM_AL 16384
#define GM_W  32768
#define GM_SMEM 49152

template <int K>
__global__ void __launch_bounds__(256, 2)
gemm_mma_kernel(const float* __restrict__ A, const __nv_bfloat16* __restrict__ wt,
                float* __restrict__ hs) {
    extern __shared__ char smc[];
    unsigned sb = smem_u32(smc);
    int tid = threadIdx.x;
    int wid = tid >> 5, lane = tid & 31;
    int row0 = blockIdx.x * 128;

    for (int i = tid; i < 1024; i += 256)
        ((float4*)(smc + GM_W))[i] = ((const float4*)wt)[i];

    constexpr int QR = K / 4;
    const float4* a4 = (const float4*)A;
    for (int i = tid; i < 128 * QR; i += 256) {
        int y = i / QR, q = i - y * QR;
        float4 v = a4[(long)(row0 + y) * QR + q];
        int off = y * 128 + q * 8;
        int sw = off ^ ((off >> 3) & 0x70);
        split_store(smc + GM_AH, smc + GM_AL, sw, v);
    }
    __syncthreads();

    int g = lane >> 2, tig = lane & 3;
    int m0 = wid * 16;
    int arow = lane & 15;
    int lext = (lane >> 4) << 4;

    float acc[8][4];
    #pragma unroll
    for (int s = 0; s < 8; s++)
        #pragma unroll
        for (int j = 0; j < 4; j++) acc[s][j] = 0.f;

    {
        int ay = m0 + arow;
        unsigned ahRow = sb + GM_AH + (unsigned)(ay * 128);
        unsigned alRow = sb + GM_AL + (unsigned)(ay * 128);
        unsigned asw = (unsigned)((ay & 7) << 4);
        #pragma unroll
        for (int k16 = 0; k16 < K / 16; k16++)
            mma_3split_k16(acc, ahRow, alRow, asw, sb + GM_W, sb + GM_W + 8192u,
                           k16, arow, lext);
    }
    __syncthreads();

    float* stg = (float*)smc;       // [128][68]
    int r0 = row0 + m0 + g, r1 = r0 + 8;
    float dv0 = g_deg[r0], dv1 = g_deg[r1];
    #pragma unroll
    for (int s = 0; s < 8; s++) {
        int col = s * 8 + tig * 2;
        float2 p0 = make_float2(acc[s][0] * dv0, acc[s][1] * dv0);
        float2 p1 = make_float2(acc[s][2] * dv1, acc[s][3] * dv1);
        *(float2*)&stg[(m0 + g) * 68 + col] = p0;
        *(float2*)&stg[(m0 + g + 8) * 68 + col] = p1;
    }
    __syncthreads();
    float4* o4 = (float4*)hs;
    #pragma unroll
    for (int jj = 0; jj < 8; jj++) {
        int idx = jj * 256 + tid;
        int mm = idx >> 4, q = idx & 15;
        o4[(long)(row0 + mm) * 16 + q] = *(const float4*)&stg[mm * 68 + q * 4];
    }
}

// ---------------- temporal (1,3) conv with FUSED sorted-gather front end ------------
// Block (b, mt). For each of 144 halo rows: agg = dinv*(self + sum srcs) + gcn bias,
// split-stored directly into the bf16 A image. Then standard 3-tap 3-split MMA.
#define TM_A_HI 0
#define TM_A_LO 18432
#define TM_B    36864
#define TM_BIAS 86016
#define TM_PART 86272
#define TM_SMEM 88320

__global__ void __launch_bounds__(256, 2)
tconv_g_kernel(const float* __restrict__ hs, const float* __restrict__ gb,
               const __nv_bfloat16* __restrict__ wt, const float* __restrict__ tb,
               float* __restrict__ out, int statOff) {
    extern __shared__ char smc[];
    unsigned sb = smem_u32(smc);
    int tid = threadIdx.x;
    int wid = tid >> 5;
    int lane = tid & 31;
    int p = blockIdx.x;
    int b = p >> 3;
    int mt = p & 7;

    for (int i = tid; i < 3072; i += 256)
        ((float4*)(smc + TM_B))[i] = ((const float4*)wt)[i];
    if (tid < 64) ((float*)(smc + TM_BIAS))[tid] = tb[tid];

    // fused gather: build agg rows (with halo) directly as bf16 hi/lo A image
    const float4* h4 = (const float4*)hs;
    for (int i = tid; i < 2304; i += 256) {
        int y = i >> 4, q = i & 15;
        int rr = mt * 128 + y - 8;
        float4 v = make_float4(0.f, 0.f, 0.f, 0.f);
        if (rr >= 0 && rr < 1024) {
            int r = b * 1024 + rr;
            int off = __ldg(&g_off[r]);
            int cnt = __ldg(&g_hist[r]);
            float dv = __ldg(&g_deg[r]);
            float4 acc = __ldg(&h4[(long)r * 16 + q]);   // self loop
            int e = 0;
            for (; e + 2 <= cnt; e += 2) {
                int s0 = __ldg(&g_srcs[off + e]);
                int s1 = __ldg(&g_srcs[off + e + 1]);
                float4 v0 = __ldg(&h4[(long)s0 * 16 + q]);
                float4 v1 = __ldg(&h4[(long)s1 * 16 + q]);
                acc.x += v0.x + v1.x; acc.y += v0.y + v1.y;
                acc.z += v0.z + v1.z; acc.w += v0.w + v1.w;
            }
            if (e < cnt) {
                int s0 = __ldg(&g_srcs[off + e]);
                float4 v0 = __ldg(&h4[(long)s0 * 16 + q]);
                acc.x += v0.x; acc.y += v0.y; acc.z += v0.z; acc.w += v0.w;
            }
            float4 bq = __ldg(&((const float4*)gb)[q]);
            v = make_float4(fmaf(acc.x, dv, bq.x), fmaf(acc.y, dv, bq.y),
                            fmaf(acc.z, dv, bq.z), fmaf(acc.w, dv, bq.w));
        }
        int off2 = y * 128 + q * 8;
        int sw = off2 ^ ((off2 >> 3) & 0x70);
        split_store(smc + TM_A_HI, smc + TM_A_LO, sw, v);
    }
    __syncthreads();

    int g = lane >> 2, tig = lane & 3;
    int m0 = wid * 16;
    int arow = lane & 15;
    int lext = (lane >> 4) << 4;

    float acc[8][4];
    #pragma unroll
    for (int s = 0; s < 8; s++)
        #pragma unroll
        for (int j = 0; j < 4; j++) acc[s][j] = 0.f;

    #pragma unroll 1
    for (int tap = 0; tap < 3; tap++) {
        int ay = tap * 8 + m0 + arow;
        unsigned ahRow = sb + TM_A_HI + (unsigned)(ay * 128);
        unsigned alRow = sb + TM_A_LO + (unsigned)(ay * 128);
        unsigned asw = (unsigned)((ay & 7) << 4);
        unsigned bh = sb + TM_B + (unsigned)(tap * 2) * 8192u;
        #pragma unroll
        for (int k16 = 0; k16 < 4; k16++)
            mma_3split_k16(acc, ahRow, alRow, asw, bh, bh + 8192u, k16, arow, lext);
    }
    __syncthreads();

    float* stg = (float*)smc;
    const float* biasS = (const float*)(smc + TM_BIAS);
    #pragma unroll
    for (int s = 0; s < 8; s++) {
        int col = s * 8 + tig * 2;
        float b0v = biasS[col], b1v = biasS[col + 1];
        int r0 = m0 + g, r1 = m0 + g + 8;
        stg[r0 * 68 + col]     = acc[s][0] + b0v;
        stg[r0 * 68 + col + 1] = acc[s][1] + b1v;
        stg[r1 * 68 + col]     = acc[s][2] + b0v;
        stg[r1 * 68 + col + 1] = acc[s][3] + b1v;
    }
    __syncthreads();

    {
        int g2 = tid >> 6, c2 = tid & 63;
        float s = 0.f, qq = 0.f;
        #pragma unroll 8
        for (int i2 = 0; i2 < 32; i2++) {
            float v = stg[(g2 * 32 + i2) * 68 + c2];
            s += v; qq = fmaf(v, v, qq);
        }
        float* ps = (float*)(smc + TM_PART);
        ps[g2 * 64 + c2] = s;
        ps[256 + g2 * 64 + c2] = qq;
    }
    __syncthreads();
    {
        const float* ps = (const float*)(smc + TM_PART);
        if (tid < 64)
            atomicAdd(&g_stats[statOff + tid], ps[tid] + ps[64 + tid] + ps[128 + tid] + ps[192 + tid]);
        else if (tid < 128) {
            int c = tid - 64;
            atomicAdd(&g_stats[statOff + 64 + c],
                      ps[256 + c] + ps[320 + c] + ps[384 + c] + ps[448 + c]);
        }
    }

    float4* out4 = (float4*)out;
    long rb16 = (long)(b * 1024 + mt * 128) * 16;
    #pragma unroll
    for (int jj = 0; jj < 8; jj++) {
        int idx = jj * 256 + tid;
        int mm = idx >> 4, q = idx & 15;
        out4[rb16 + mm * 16 + q] = *(const float4*)&stg[mm * 68 + q * 4];
    }
}

// ---------------- layer-1 epilogue fused with layer-2 GEMM ----------------
#define F2_AH   0
#define F2_AL   16384
#define F2_OW   32768
#define F2_GW   49152
#define F2_MISC 65536
#define F2_SMEM (F2_MISC + 1280)           // 66816

__global__ void __launch_bounds__(256, 2)
fused_gemm2_kernel(const float* __restrict__ tmp, const __nv_bfloat16* __restrict__ owt,
                   const __nv_bfloat16* __restrict__ gwt, const float* __restrict__ ob,
                   const float* __restrict__ gam, const float* __restrict__ beta,
                   float* __restrict__ hs2) {
    extern __shared__ char smc[];
    unsigned sb = smem_u32(smc);
    int tid = threadIdx.x;
    int wid = tid >> 5, lane = tid & 31;
    int p = blockIdx.x;                 // 1024
    int b = p >> 3, n = p & 7;

    float* scS = (float*)(smc + F2_MISC);
    float* shS = scS + 64;
    float* obsS = scS + 128;
    float* dvS = scS + 192;             // [128]

    if (tid < 64) {
        const float inv_cnt = 1.0f / 131072.0f;
        float mu = g_stats[tid] * inv_cnt;
        float var = g_stats[64 + tid] * inv_cnt - mu * mu;
        float scv = gam[tid] * rsqrtf(var + 1e-5f);
        scS[tid] = scv;
        shS[tid] = beta[tid] - mu * scv;
        obsS[tid] = ob[tid];
    }
    if (tid < 128)
        dvS[tid] = g_deg[b * 1024 + (tid >> 1) * 16 + n * 2 + (tid & 1)];
    for (int i = tid; i < 1024; i += 256) {
        ((float4*)(smc + F2_OW))[i] = ((const float4*)owt)[i];
        ((float4*)(smc + F2_GW))[i] = ((const float4*)gwt)[i];
    }
    __syncthreads();

    const float4* t4 = (const float4*)tmp;
    for (int i = tid; i < 2048; i += 256) {
        int y = i >> 4, q = i & 15;
        float4 v = t4[((long)(b * 128 + y) * 8 + n) * 16 + q];
        float4 sc4 = *(const float4*)&scS[q * 4];
        float4 sh4 = *(const float4*)&shS[q * 4];
        float4 r;
        r.x = fmaxf(0.f, fmaf(v.x, sc4.x, sh4.x));
        r.y = fmaxf(0.f, fmaf(v.y, sc4.y, sh4.y));
        r.z = fmaxf(0.f, fmaf(v.z, sc4.z, sh4.z));
        r.w = fmaxf(0.f, fmaf(v.w, sc4.w, sh4.w));
        int off = y * 128 + q * 8;
        int sw = off ^ ((off >> 3) & 0x70);
        split_store(smc + F2_AH, smc + F2_AL, sw, r);
    }
    __syncthreads();

    int g = lane >> 2, tig = lane & 3;
    int m0 = wid * 16;

    float acc[8][4];
    #pragma unroll
    for (int s = 0; s < 8; s++)
        #pragma unroll
        for (int j = 0; j < 4; j++) acc[s][j] = 0.f;
    mma_3split_64(acc, sb, F2_AH, F2_AL, F2_OW, m0, lane);
    __syncthreads();

    int th = (m0 >= 64) ? 1 : 0;
    int tp0 = (m0 + g) & 63;
    #pragma unroll
    for (int s = 0; s < 8; s++) {
        int c2 = s * 8 + tig * 2;
        float o0 = obsS[c2], o1 = obsS[c2 + 1];
        int zr0 = 2 * c2 + th, zr1 = 2 * (c2 + 1) + th;
        float v00 = tanh_ap(acc[s][0] + o0);
        float v01 = tanh_ap(acc[s][1] + o1);
        float v10 = tanh_ap(acc[s][2] + o0);
        float v11 = tanh_ap(acc[s][3] + o1);
        int o00 = zr0 * 128 + tp0 * 2;       o00 ^= ((o00 >> 3) & 0x70);
        int o01 = zr1 * 128 + tp0 * 2;       o01 ^= ((o01 >> 3) & 0x70);
        int o10 = zr0 * 128 + (tp0 + 8) * 2; o10 ^= ((o10 >> 3) & 0x70);
        int o11 = zr1 * 128 + (tp0 + 8) * 2; o11 ^= ((o11 >> 3) & 0x70);
        split_store1(smc + F2_AH, smc + F2_AL, o00, v00);
        split_store1(smc + F2_AH, smc + F2_AL, o01, v01);
        split_store1(smc + F2_AH, smc + F2_AL, o10, v10);
        split_store1(smc + F2_AH, smc + F2_AL, o11, v11);
    }
    __syncthreads();

    float acc2[8][4];
    #pragma unroll
    for (int s = 0; s < 8; s++)
        #pragma unroll
        for (int j = 0; j < 4; j++) acc2[s][j] = 0.f;
    mma_3split_64(acc2, sb, F2_AH, F2_AL, F2_GW, m0, lane);
    __syncthreads();

    float* stgF = (float*)smc;
    {
        int zr0 = m0 + g, zr1 = m0 + g + 8;
        float dv0 = dvS[zr0], dv1 = dvS[zr1];
        #pragma unroll
        for (int s = 0; s < 8; s++) {
            int col = s * 8 + tig * 2;
            *(float2*)&stgF[zr0 * 68 + col] = make_float2(acc2[s][0] * dv0, acc2[s][1] * dv0);
            *(float2*)&stgF[zr1 * 68 + col] = make_float2(acc2[s][2] * dv1, acc2[s][3] * dv1);
        }
    }
    __syncthreads();
    float4* o4 = (float4*)hs2;
    long base = (long)b * 1024 + n * 2;
    #pragma unroll
    for (int jj = 0; jj < 8; jj++) {
        int idx = jj * 256 + tid;
        int zr = idx >> 4, q = idx & 15;
        long r2 = base + (zr >> 1) * 16 + (zr & 1);
        o4[r2 * 16 + q] = *(const float4*)&stgF[zr * 68 + q * 4];
    }
}

// ---------------- layer-2 final: bn->relu->1x1->tanh->regression reduce ------------
// Tail also re-zeroes g_hist for the NEXT call (dead here; graph-replay invariant).
#define FM_AH 0
#define FM_AL 16384
#define FM_W  32768
#define FM_MISC 49152
#define FM_SRED (FM_MISC + 768)
#define FM_SMEM 50176

__global__ void __launch_bounds__(256, 2)
fused_final_kernel(const float* __restrict__ tmp, const __nv_bfloat16* __restrict__ wt,
                   const float* __restrict__ ob, const float* __restrict__ gam,
                   const float* __restrict__ beta, float* __restrict__ z, int statOff) {
    extern __shared__ char smc[];
    unsigned sb = smem_u32(smc);
    int tid = threadIdx.x;
    int wid = tid >> 5, lane = tid & 31;
    int row0 = blockIdx.x * 128;

    float* scS = (float*)(smc + FM_MISC);
    float* shS = scS + 64;
    float* obsS = scS + 128;
    float* sred = (float*)(smc + FM_SRED);

    if (tid < 64) {
        const float inv_cnt = 1.0f / 131072.0f;
        float mu = g_stats[statOff + tid] * inv_cnt;
        float var = g_stats[statOff + 64 + tid] * inv_cnt - mu * mu;
        float scv = gam[tid] * rsqrtf(var + 1e-5f);
        scS[tid] = scv;
        shS[tid] = beta[tid] - mu * scv;
        obsS[tid] = ob[tid];
        sred[tid] = 0.f;
    }
    for (int i = tid; i < 1024; i += 256)
        ((float4*)(smc + FM_W))[i] = ((const float4*)wt)[i];
    __syncthreads();

    const float4* t4 = (const float4*)tmp;
    for (int i = tid; i < 2048; i += 256) {
        int y = i >> 4, q = i & 15;
        float4 v = t4[(long)(row0 + y) * 16 + q];
        float4 sc4 = *(const float4*)&scS[q * 4];
        float4 sh4 = *(const float4*)&shS[q * 4];
        float4 r;
        r.x = fmaxf(0.f, fmaf(v.x, sc4.x, sh4.x));
        r.y = fmaxf(0.f, fmaf(v.y, sc4.y, sh4.y));
        r.z = fmaxf(0.f, fmaf(v.z, sc4.z, sh4.z));
        r.w = fmaxf(0.f, fmaf(v.w, sc4.w, sh4.w));
        int off = y * 128 + q * 8;
        int sw = off ^ ((off >> 3) & 0x70);
        split_store(smc + FM_AH, smc + FM_AL, sw, r);
    }
    __syncthreads();

    int g = lane >> 2, tig = lane & 3;
    int m0 = wid * 16;

    float acc[8][4];
    #pragma unroll
    for (int s = 0; s < 8; s++)
        #pragma unroll
        for (int j = 0; j < 4; j++) acc[s][j] = 0.f;
    mma_3split_64(acc, sb, FM_AH, FM_AL, FM_W, m0, lane);

    int bq = row0 >> 10;
    int t0 = ((row0 + m0) >> 3) & 127;

    float w0 = g_wbar[t0 & 63] * 0.0078125f;
    float w1 = g_wbar[(t0 + 1) & 63] * 0.0078125f;
    float s0 = 0.f, s1 = 0.f;
    #pragma unroll
    for (int s = 0; s < 8; s++) {
        int c2 = s * 8 + tig * 2;
        float o0 = obsS[c2], o1 = obsS[c2 + 1];
        s0 += tanh_ap(acc[s][0] + o0) + tanh_ap(acc[s][1] + o1);
        s1 += tanh_ap(acc[s][2] + o0) + tanh_ap(acc[s][3] + o1);
    }
    float part = w0 * s0 + w1 * s1;
    part += __shfl_xor_sync(0xffffffffu, part, 1);
    part += __shfl_xor_sync(0xffffffffu, part, 2);
    part += __shfl_xor_sync(0xffffffffu, part, 16);
    int th = (t0 >> 6) & 1;
    if (tig == 0 && g < 4) {
        int idx = (2 * g + th) & 7;
        sred[idx * 8 + wid] = part;
    }
    __syncthreads();
    if (tid < 8) {
        float ssum = 0.f;
        #pragma unroll
        for (int w = 0; w < 8; w++) ssum += sred[tid * 8 + w];
        atomicAdd(&z[bq * 8 + tid], ssum);
    }

    // re-arm next call: zero g_hist (dead in this kernel; all writers/readers done)
    int zi = blockIdx.x * 256 + tid;
    if (zi < NROWS) g_hist[zi] = 0;
}

// ---------------- host launcher ----------------
extern "C" void kernel_launch(void* const* d_in, const int* in_sizes, int n_in,
                              void* d_out, int out_size) {
    const float* x      = (const float*)d_in[0];
    const int*   ei     = (const int*)d_in[1];
    const float* gcn1_w = (const float*)d_in[2];
    const float* gcn1_b = (const float*)d_in[3];
    const float* t1_w   = (const float*)d_in[4];
    const float* t1_b   = (const float*)d_in[5];
    const float* bn1_g  = (const float*)d_in[6];
    const float* bn1_b  = (const float*)d_in[7];
    const float* o1_w   = (const float*)d_in[8];
    const float* o1_b   = (const float*)d_in[9];
    const float* gcn2_w = (const float*)d_in[10];
    const float* gcn2_b = (const float*)d_in[11];
    const float* t2_w   = (const float*)d_in[12];
    const float* t2_b   = (const float*)d_in[13];
    const float* bn2_g  = (const float*)d_in[14];
    const float* bn2_b  = (const float*)d_in[15];
    const float* o2_w   = (const float*)d_in[16];
    const float* o2_b   = (const float*)d_in[17];
    const float* reg_w  = (const float*)d_in[18];
    const float* reg_b  = (const float*)d_in[19];
    float* out = (float*)d_out;

    const int* src = ei;
    const int* dst = ei + EDGES;

    cudaFuncSetAttribute(tconv_g_kernel, cudaFuncAttributeMaxDynamicSharedMemorySize, TM_SMEM);
    cudaFuncSetAttribute(gemm_mma_kernel<32>, cudaFuncAttributeMaxDynamicSharedMemorySize, GM_SMEM);
    cudaFuncSetAttribute(fused_gemm2_kernel, cudaFuncAttributeMaxDynamicSharedMemorySize, F2_SMEM);
    cudaFuncSetAttribute(fused_final_kernel, cudaFuncAttributeMaxDynamicSharedMemorySize, FM_SMEM);

    float* bufA; cudaGetSymbolAddress((void**)&bufA, g_bufA);
    float* bufB; cudaGetSymbolAddress((void**)&bufB, g_bufB);
    float* bufC; cudaGetSymbolAddress((void**)&bufC, g_bufC);
    __nv_bfloat16* wt1; cudaGetSymbolAddress((void**)&wt1, g_wt1);
    __nv_bfloat16* wt2; cudaGetSymbolAddress((void**)&wt2, g_wt2);
    __nv_bfloat16* gw1; cudaGetSymbolAddress((void**)&gw1, g_gw1);
    __nv_bfloat16* gw2; cudaGetSymbolAddress((void**)&gw2, g_gw2);
    __nv_bfloat16* ow1; cudaGetSymbolAddress((void**)&ow1, g_ow1);
    __nv_bfloat16* ow2; cudaGetSymbolAddress((void**)&ow2, g_ow2);

    // sort + weight prep (g_hist was zeroed by previous call's fused_final)
    phist_kernel<<<EDGES / 256, 256>>>(dst, reg_w, reg_b, t1_w, t2_w,
                                       gcn1_w, gcn2_w, o1_w, o2_w);
    scan1_kernel<<<128, 256>>>();
    scan3_kernel<<<NROWS / 256, 256>>>(reg_b, out);
    scatter_kernel<<<EDGES / 256, 256>>>(src, dst);

    // -------- layer 1 --------
    gemm_mma_kernel<32><<<NROWS / 128, 256, GM_SMEM>>>(x, gw1, bufA);
    tconv_g_kernel<<<1024, 256, TM_SMEM>>>(bufA, gcn1_b, wt1, t1_b, bufC, 0);
    fused_gemm2_kernel<<<1024, 256, F2_SMEM>>>(bufC, ow1, gw2, o1_b, bn1_g, bn1_b, bufA);

    // -------- layer 2 --------
    tconv_g_kernel<<<1024, 256, TM_SMEM>>>(bufA, gcn2_b, wt2, t2_b, bufB, 128);
    fused_final_kernel<<<NROWS / 128, 256, FM_SMEM>>>(bufB, ow2, o2_b, bn2_g, bn2_b, out, 128);
}

// round 16
// speedup vs baseline: 1.1823x; 1.1823x over previous
#include <cuda_runtime.h>
#include <cuda_bf16.h>
#include <cstdint>
#include <stdint.h>
#include <math.h>

#define NROWS 131072
#define EDGES 1048576

// ---------------- scratch (device globals) ----------------
__device__ float g_bufA[NROWS * 64];
__device__ float g_bufB[NROWS * 64];
__device__ float g_bufC[NROWS * 64];
__device__ float g_deg[NROWS];      // dinv
__device__ int   g_hist[NROWS];     // zeroed at END of pipeline (fused_final tail)
__device__ int   g_off[NROWS];
__device__ int   g_cursor[NROWS];
__device__ int   g_bsum[128];
__device__ int   g_srcs[EDGES];
__device__ float g_stats[256];      // zeroed early (scan1 tail)
__device__ float g_wbar[65];
// bf16 weight tiles, XOR-swizzled 128B rows, hi tile then lo tile
__device__ __align__(16) __nv_bfloat16 g_wt1[24576];  // tconv l1: [tap*2+split][64x64]
__device__ __align__(16) __nv_bfloat16 g_wt2[24576];  // tconv l2
__device__ __align__(16) __nv_bfloat16 g_gw1[8192];   // gcn1_w [32k x 64n]
__device__ __align__(16) __nv_bfloat16 g_gw2[8192];   // gcn2_w [64k x 64n]
__device__ __align__(16) __nv_bfloat16 g_ow1[8192];   // o1_w^T [64c x 64c2]
__device__ __align__(16) __nv_bfloat16 g_ow2[8192];   // o2_w^T

typedef unsigned long long ull;
__device__ __forceinline__ float tanh_ap(float x) {
    float y; asm("tanh.approx.f32 %0,%1;" : "=f"(y) : "f"(x)); return y;
}

// ---------------- mma.sync helpers ----------------
__device__ __forceinline__ unsigned smem_u32(const void* p) {
    unsigned a;
    asm("{ .reg .u64 t; cvta.to.shared.u64 t, %1; cvt.u32.u64 %0, t; }" : "=r"(a) : "l"(p));
    return a;
}
__device__ __forceinline__ void ldsm4(unsigned& r0, unsigned& r1, unsigned& r2, unsigned& r3,
                                      unsigned addr) {
    asm volatile("ldmatrix.sync.aligned.m8n8.x4.shared.b16 {%0,%1,%2,%3}, [%4];"
                 : "=r"(r0), "=r"(r1), "=r"(r2), "=r"(r3) : "r"(addr));
}
__device__ __forceinline__ void ldsm4t(unsigned& r0, unsigned& r1, unsigned& r2, unsigned& r3,
                                       unsigned addr) {
    asm volatile("ldmatrix.sync.aligned.m8n8.x4.trans.shared.b16 {%0,%1,%2,%3}, [%4];"
                 : "=r"(r0), "=r"(r1), "=r"(r2), "=r"(r3) : "r"(addr));
}
__device__ __forceinline__ void mma_bf16(float* c, unsigned a0, unsigned a1, unsigned a2,
                                         unsigned a3, unsigned b0, unsigned b1) {
    asm volatile(
        "mma.sync.aligned.m16n8k16.row.col.f32.bf16.bf16.f32 "
        "{%0,%1,%2,%3}, {%4,%5,%6,%7}, {%8,%9}, {%0,%1,%2,%3};"
        : "+f"(c[0]), "+f"(c[1]), "+f"(c[2]), "+f"(c[3])
        : "r"(a0), "r"(a1), "r"(a2), "r"(a3), "r"(b0), "r"(b1));
}
__device__ __forceinline__ void split_store(char* hi, char* lo, int sw, float4 v) {
    __nv_bfloat162 h01 = __floats2bfloat162_rn(v.x, v.y);
    __nv_bfloat162 h23 = __floats2bfloat162_rn(v.z, v.w);
    float lx = v.x - __bfloat162float(h01.x);
    float ly = v.y - __bfloat162float(h01.y);
    float lz = v.z - __bfloat162float(h23.x);
    float lw = v.w - __bfloat162float(h23.y);
    __nv_bfloat162 l01 = __floats2bfloat162_rn(lx, ly);
    __nv_bfloat162 l23 = __floats2bfloat162_rn(lz, lw);
    uint2 hp, lp;
    hp.x = *(unsigned*)&h01; hp.y = *(unsigned*)&h23;
    lp.x = *(unsigned*)&l01; lp.y = *(unsigned*)&l23;
    *(uint2*)(hi + sw) = hp;
    *(uint2*)(lo + sw) = lp;
}
__device__ __forceinline__ void split_store1(char* hi, char* lo, int sw, float v) {
    __nv_bfloat16 h = __float2bfloat16_rn(v);
    __nv_bfloat16 l = __float2bfloat16_rn(v - __bfloat162float(h));
    *(__nv_bfloat16*)(hi + sw) = h;
    *(__nv_bfloat16*)(lo + sw) = l;
}

// one k16 step of the 3-term bf16 split GEMM: Ah*Bh + Ah*Bl + Al*Bh
__device__ __forceinline__ void mma_3split_k16(float acc[8][4], unsigned ahRow, unsigned alRow,
                                               unsigned asw, unsigned bhTile, unsigned blTile,
                                               int k16, int arow, int lext) {
    unsigned a0, a1, a2, a3, c0, c1, c2, c3;
    unsigned kb = (((unsigned)(k16 * 32)) + lext) ^ asw;
    ldsm4(a0, a1, a2, a3, ahRow + kb);
    ldsm4(c0, c1, c2, c3, alRow + kb);
    int krow = k16 * 16 + arow;
    unsigned bro = (unsigned)(krow * 128);
    unsigned bsw = (unsigned)((krow & 7) << 4);
    #pragma unroll
    for (int nn = 0; nn < 4; nn++) {
        unsigned b0, b1, b2, b3, d0, d1, d2, d3;
        unsigned nb = (((unsigned)(nn * 32)) + lext) ^ bsw;
        ldsm4t(b0, b1, b2, b3, bhTile + bro + nb);
        ldsm4t(d0, d1, d2, d3, blTile + bro + nb);
        mma_bf16(acc[2 * nn],     a0, a1, a2, a3, b0, b1);
        mma_bf16(acc[2 * nn + 1], a0, a1, a2, a3, b2, b3);
        mma_bf16(acc[2 * nn],     a0, a1, a2, a3, d0, d1);
        mma_bf16(acc[2 * nn + 1], a0, a1, a2, a3, d2, d3);
        mma_bf16(acc[2 * nn],     c0, c1, c2, c3, b0, b1);
        mma_bf16(acc[2 * nn + 1], c0, c1, c2, c3, b2, b3);
    }
}

__device__ __forceinline__ void mma_3split_64(float acc[8][4], unsigned sb, unsigned ahOff,
                                              unsigned alOff, unsigned wOff, int m0, int lane) {
    int arow = lane & 15;
    int lext = (lane >> 4) << 4;
    int ay = m0 + arow;
    unsigned ahRow = sb + ahOff + (unsigned)(ay * 128);
    unsigned alRow = sb + alOff + (unsigned)(ay * 128);
    unsigned asw = (unsigned)((ay & 7) << 4);
    #pragma unroll
    for (int k16 = 0; k16 < 4; k16++)
        mma_3split_k16(acc, ahRow, alRow, asw, sb + wOff, sb + wOff + 8192u, k16, arow, lext);
}

// ---------------- phist: hist atomics + weight prep (merged prologue) ----------------
__global__ void phist_kernel(const int* __restrict__ dst,
                             const float* __restrict__ rw, const float* __restrict__ rb,
                             const float* __restrict__ t1w, const float* __restrict__ t2w,
                             const float* __restrict__ g1w, const float* __restrict__ g2w,
                             const float* __restrict__ o1w, const float* __restrict__ o2w) {
    int i = blockIdx.x * blockDim.x + threadIdx.x;    // 0 .. EDGES-1
    atomicAdd(&g_hist[dst[i]], 1);

    if (i < 12288) {
        int k = i >> 12;
        int r = i & 4095;
        int c2 = r >> 6, c = r & 63;
        int off = c * 128 + c2 * 2;
        int sw = off ^ ((off >> 3) & 0x70);
        int idx = sw >> 1;
        float w1 = t1w[(c2 * 64 + c) * 3 + k];
        float w2 = t2w[(c2 * 64 + c) * 3 + k];
        __nv_bfloat16 h1 = __float2bfloat16_rn(w1);
        __nv_bfloat16 h2 = __float2bfloat16_rn(w2);
        g_wt1[(k * 2 + 0) * 4096 + idx] = h1;
        g_wt1[(k * 2 + 1) * 4096 + idx] = __float2bfloat16_rn(w1 - __bfloat162float(h1));
        g_wt2[(k * 2 + 0) * 4096 + idx] = h2;
        g_wt2[(k * 2 + 1) * 4096 + idx] = __float2bfloat16_rn(w2 - __bfloat162float(h2));
    } else if (i < 16384) {
        int j = i - 12288;
        int k = j >> 6, n = j & 63;
        int off = k * 128 + n * 2;
        int sw = off ^ ((off >> 3) & 0x70);
        int idx = sw >> 1;
        float w = g2w[k * 64 + n];
        __nv_bfloat16 h = __float2bfloat16_rn(w);
        g_gw2[idx] = h;
        g_gw2[4096 + idx] = __float2bfloat16_rn(w - __bfloat162float(h));
    } else if (i < 20480) {
        int j = i - 16384;
        int c = j >> 6, c2 = j & 63;
        int off = c * 128 + c2 * 2;
        int sw = off ^ ((off >> 3) & 0x70);
        int idx = sw >> 1;
        float w = o1w[c2 * 64 + c];
        __nv_bfloat16 h = __float2bfloat16_rn(w);
        g_ow1[idx] = h;
        g_ow1[4096 + idx] = __float2bfloat16_rn(w - __bfloat162float(h));
    } else if (i < 24576) {
        int j = i - 20480;
        int c = j >> 6, c2 = j & 63;
        int off = c * 128 + c2 * 2;
        int sw = off ^ ((off >> 3) & 0x70);
        int idx = sw >> 1;
        float w = o2w[c2 * 64 + c];
        __nv_bfloat16 h = __float2bfloat16_rn(w);
        g_ow2[idx] = h;
        g_ow2[4096 + idx] = __float2bfloat16_rn(w - __bfloat162float(h));
    } else if (i < 26624) {
        int j = i - 24576;
        int k = j >> 6, n = j & 63;
        int off = k * 128 + n * 2;
        int sw = off ^ ((off >> 3) & 0x70);
        int idx = sw >> 1;
        float w = g1w[k * 64 + n];
        __nv_bfloat16 h = __float2bfloat16_rn(w);
        g_gw1[idx] = h;
        g_gw1[4096 + idx] = __float2bfloat16_rn(w - __bfloat162float(h));
    }
    if (i < 64) {
        float s = 0.f;
        #pragma unroll
        for (int j = 0; j < 8; j++) s += rw[i * 8 + j];
        g_wbar[i] = s * 0.125f;
    }
    if (i == 64) {
        float s = 0.f;
        #pragma unroll
        for (int j = 0; j < 8; j++) s += rb[j];
        g_wbar[64] = s * 0.125f;
    }
}

__global__ void scan1_kernel() {
    __shared__ int sh[256];
    int tid = threadIdx.x;
    int base = blockIdx.x * 1024 + tid * 4;
    int4 v = *(const int4*)&g_hist[base];
    int s0 = v.x, s1 = s0 + v.y, s2 = s1 + v.z, s3 = s2 + v.w;
    sh[tid] = s3;
    __syncthreads();
    #pragma unroll
    for (int o = 1; o < 256; o <<= 1) {
        int t = (tid >= o) ? sh[tid - o] : 0;
        __syncthreads();
        sh[tid] += t;
        __syncthreads();
    }
    int excl = tid ? sh[tid - 1] : 0;
    int4 w = make_int4(excl, excl + s0, excl + s1, excl + s2);
    *(int4*)&g_off[base] = w;
    if (tid == 255) g_bsum[blockIdx.x] = sh[255];
    int gi = blockIdx.x * 256 + tid;
    if (gi < 256) g_stats[gi] = 0.0f;
}

// scan3: local re-scan of the 128 segment sums + dinv/cursor/out-init
__global__ void scan3_kernel(const float* __restrict__ rb, float* __restrict__ out) {
    __shared__ int bs[128];
    int tid = threadIdx.x;
    if (tid < 128) bs[tid] = g_bsum[tid];
    __syncthreads();
    #pragma unroll
    for (int o = 1; o < 128; o <<= 1) {
        int t = (tid < 128 && tid >= o) ? bs[tid - o] : 0;
        __syncthreads();
        if (tid < 128) bs[tid] += t;
        __syncthreads();
    }
    int i = blockIdx.x * blockDim.x + tid;
    if (i < NROWS) {
        int seg = i >> 10;
        int o = g_off[i] + (seg ? bs[seg - 1] : 0);
        g_off[i] = o;
        g_cursor[i] = o;
        g_deg[i] = rsqrtf((float)g_hist[i] + 1.0f);
    }
    if (i < 1024) {
        float s = 0.f;
        #pragma unroll
        for (int j = 0; j < 8; j++) s += rb[j];
        out[i] = s * 0.125f;
    }
}

__global__ void scatter_kernel(const int* __restrict__ src, const int* __restrict__ dst) {
    int e = blockIdx.x * blockDim.x + threadIdx.x;
    if (e < EDGES) {
        int d = dst[e];
        int pos = atomicAdd(&g_cursor[d], 1);
        g_srcs[pos] = src[e];
    }
}

// ---------------- GEMM hs = (A@W)*dinv via mma.sync (layer 1 input) ----------------
#define GM_AH 0
#define GM_AL 16384
#define GM_W  32768
#define GM_SMEM 49152

template <int K>
__global__ void __launch_bounds__(256, 2)
gemm_mma_kernel(const float* __restrict__ A, const __nv_bfloat16* __restrict__ wt,
                float* __restrict__ hs) {
    extern __shared__ char smc[];
    unsigned sb = smem_u32(smc);
    int tid = threadIdx.x;
    int wid = tid >> 5, lane = tid & 31;
    int row0 = blockIdx.x * 128;

    for (int i = tid; i < 1024; i += 256)
        ((float4*)(smc + GM_W))[i] = ((const float4*)wt)[i];

    constexpr int QR = K / 4;
    const float4* a4 = (const float4*)A;
    for (int i = tid; i < 128 * QR; i += 256) {
        int y = i / QR, q = i - y * QR;
        float4 v = a4[(long)(row0 + y) * QR + q];
        int off = y * 128 + q * 8;
        int sw = off ^ ((off >> 3) & 0x70);
        split_store(smc + GM_AH, smc + GM_AL, sw, v);
    }
    __syncthreads();

    int g = lane >> 2, tig = lane & 3;
    int m0 = wid * 16;
    int arow = lane & 15;
    int lext = (lane >> 4) << 4;

    float acc[8][4];
    #pragma unroll
    for (int s = 0; s < 8; s++)
        #pragma unroll
        for (int j = 0; j < 4; j++) acc[s][j] = 0.f;

    {
        int ay = m0 + arow;
        unsigned ahRow = sb + GM_AH + (unsigned)(ay * 128);
        unsigned alRow = sb + GM_AL + (unsigned)(ay * 128);
        unsigned asw = (unsigned)((ay & 7) << 4);
        #pragma unroll
        for (int k16 = 0; k16 < K / 16; k16++)
            mma_3split_k16(acc, ahRow, alRow, asw, sb + GM_W, sb + GM_W + 8192u,
                           k16, arow, lext);
    }
    __syncthreads();

    float* stg = (float*)smc;       // [128][68]
    int r0 = row0 + m0 + g, r1 = r0 + 8;
    float dv0 = g_deg[r0], dv1 = g_deg[r1];
    #pragma unroll
    for (int s = 0; s < 8; s++) {
        int col = s * 8 + tig * 2;
        float2 p0 = make_float2(acc[s][0] * dv0, acc[s][1] * dv0);
        float2 p1 = make_float2(acc[s][2] * dv1, acc[s][3] * dv1);
        *(float2*)&stg[(m0 + g) * 68 + col] = p0;
        *(float2*)&stg[(m0 + g + 8) * 68 + col] = p1;
    }
    __syncthreads();
    float4* o4 = (float4*)hs;
    #pragma unroll
    for (int jj = 0; jj < 8; jj++) {
        int idx = jj * 256 + tid;
        int mm = idx >> 4, q = idx & 15;
        o4[(long)(row0 + mm) * 16 + q] = *(const float4*)&stg[mm * 68 + q * 4];
    }
}

// ---------------- sorted gather aggregation (atomic-free, standalone) ----------------
__global__ void gather_agg_kernel(const float* __restrict__ hs, const float* __restrict__ bias,
                                  float* __restrict__ agg) {
    int tid = threadIdx.x;              // 256
    int r = blockIdx.x * 16 + (tid >> 4);
    int q = tid & 15;
    int off = __ldg(&g_off[r]);
    int cnt = __ldg(&g_hist[r]);
    float dv = g_deg[r];
    const float4* h4 = (const float4*)hs;

    float4 acc = __ldg(&h4[(long)r * 16 + q]);
    int i = 0;
    for (; i + 2 <= cnt; i += 2) {
        int s0 = __ldg(&g_srcs[off + i]);
        int s1 = __ldg(&g_srcs[off + i + 1]);
        float4 v0 = __ldg(&h4[(long)s0 * 16 + q]);
        float4 v1 = __ldg(&h4[(long)s1 * 16 + q]);
        acc.x += v0.x + v1.x; acc.y += v0.y + v1.y;
        acc.z += v0.z + v1.z; acc.w += v0.w + v1.w;
    }
    if (i < cnt) {
        int s0 = __ldg(&g_srcs[off + i]);
        float4 v0 = __ldg(&h4[(long)s0 * 16 + q]);
        acc.x += v0.x; acc.y += v0.y; acc.z += v0.z; acc.w += v0.w;
    }
    float4 b = __ldg(&((const float4*)bias)[q]);
    float4 o = make_float4(fmaf(acc.x, dv, b.x), fmaf(acc.y, dv, b.y),
                           fmaf(acc.z, dv, b.z), fmaf(acc.w, dv, b.w));
    ((float4*)agg)[(long)r * 16 + q] = o;
}

// ---------------- temporal (1,3) conv via mma.sync ----------------
#define TM_A_HI 0
#define TM_A_LO 18432
#define TM_B    36864
#define TM_BIAS 86016
#define TM_PART 86272
#define TM_SMEM 88320

__global__ void __launch_bounds__(256, 2)
tconv_mma_kernel(const float* __restrict__ in, const __nv_bfloat16* __restrict__ wt,
                 const float* __restrict__ tb, float* __restrict__ out, int statOff) {
    extern __shared__ char smc[];
    unsigned sb = smem_u32(smc);
    int tid = threadIdx.x;
    int wid = tid >> 5;
    int lane = tid & 31;
    int p = blockIdx.x;
    int b = p >> 3;
    int mt = p & 7;

    for (int i = tid; i < 3072; i += 256)
        ((float4*)(smc + TM_B))[i] = ((const float4*)wt)[i];
    if (tid < 64) ((float*)(smc + TM_BIAS))[tid] = tb[tid];

    const float4* in4 = (const float4*)in;
    for (int i = tid; i < 2304; i += 256) {
        int y = i >> 4, q = i & 15;
        int rr = mt * 128 + y - 8;
        float4 v = make_float4(0.f, 0.f, 0.f, 0.f);
        if (rr >= 0 && rr < 1024) v = in4[(long)(b * 1024 + rr) * 16 + q];
        int off = y * 128 + q * 8;
        int sw = off ^ ((off >> 3) & 0x70);
        split_store(smc + TM_A_HI, smc + TM_A_LO, sw, v);
    }
    __syncthreads();

    int g = lane >> 2, tig = lane & 3;
    int m0 = wid * 16;
    int arow = lane & 15;
    int lext = (lane >> 4) << 4;

    float acc[8][4];
    #pragma unroll
    for (int s = 0; s < 8; s++)
        #pragma unroll
        for (int j = 0; j < 4; j++) acc[s][j] = 0.f;

    #pragma unroll 1
    for (int tap = 0; tap < 3; tap++) {
        int ay = tap * 8 + m0 + arow;
        unsigned ahRow = sb + TM_A_HI + (unsigned)(ay * 128);
        unsigned alRow = sb + TM_A_LO + (unsigned)(ay * 128);
        unsigned asw = (unsigned)((ay & 7) << 4);
        unsigned bh = sb + TM_B + (unsigned)(tap * 2) * 8192u;
        #pragma unroll
        for (int k16 = 0; k16 < 4; k16++)
            mma_3split_k16(acc, ahRow, alRow, asw, bh, bh + 8192u, k16, arow, lext);
    }
    __syncthreads();

    float* stg = (float*)smc;
    const float* biasS = (const float*)(smc + TM_BIAS);
    #pragma unroll
    for (int s = 0; s < 8; s++) {
        int col = s * 8 + tig * 2;
        float b0v = biasS[col], b1v = biasS[col + 1];
        int r0 = m0 + g, r1 = m0 + g + 8;
        stg[r0 * 68 + col]     = acc[s][0] + b0v;
        stg[r0 * 68 + col + 1] = acc[s][1] + b1v;
        stg[r1 * 68 + col]     = acc[s][2] + b0v;
        stg[r1 * 68 + col + 1] = acc[s][3] + b1v;
    }
    __syncthreads();

    {
        int g2 = tid >> 6, c2 = tid & 63;
        float s = 0.f, qq = 0.f;
        #pragma unroll 8
        for (int i2 = 0; i2 < 32; i2++) {
            float v = stg[(g2 * 32 + i2) * 68 + c2];
            s += v; qq = fmaf(v, v, qq);
        }
        float* ps = (float*)(smc + TM_PART);
        ps[g2 * 64 + c2] = s;
        ps[256 + g2 * 64 + c2] = qq;
    }
    __syncthreads();
    {
        const float* ps = (const float*)(smc + TM_PART);
        if (tid < 64)
            atomicAdd(&g_stats[statOff + tid], ps[tid] + ps[64 + tid] + ps[128 + tid] + ps[192 + tid]);
        else if (tid < 128) {
            int c = tid - 64;
            atomicAdd(&g_stats[statOff + 64 + c],
                      ps[256 + c] + ps[320 + c] + ps[384 + c] + ps[448 + c]);
        }
    }

    float4* out4 = (float4*)out;
    long rb16 = (long)(b * 1024 + mt * 128) * 16;
    #pragma unroll
    for (int jj = 0; jj < 8; jj++) {
        int idx = jj * 256 + tid;
        int mm = idx >> 4, q = idx & 15;
        out4[rb16 + mm * 16 + q] = *(const float4*)&stg[mm * 68 + q * 4];
    }
}

// ---------------- layer-1 epilogue fused with layer-2 GEMM ----------------
#define F2_AH   0
#define F2_AL   16384
#define F2_OW   32768
#define F2_GW   49152
#define F2_MISC 65536
#define F2_SMEM (F2_MISC + 1280)           // 66816

__global__ void __launch_bounds__(256, 2)
fused_gemm2_kernel(const float* __restrict__ tmp, const __nv_bfloat16* __restrict__ owt,
                   const __nv_bfloat16* __restrict__ gwt, const float* __restrict__ ob,
                   const float* __restrict__ gam, const float* __restrict__ beta,
                   float* __restrict__ hs2) {
    extern __shared__ char smc[];
    unsigned sb = smem_u32(smc);
    int tid = threadIdx.x;
    int wid = tid >> 5, lane = tid & 31;
    int p = blockIdx.x;                 // 1024
    int b = p >> 3, n = p & 7;

    float* scS = (float*)(smc + F2_MISC);
    float* shS = scS + 64;
    float* obsS = scS + 128;
    float* dvS = scS + 192;             // [128]

    if (tid < 64) {
        const float inv_cnt = 1.0f / 131072.0f;
        float mu = g_stats[tid] * inv_cnt;
        float var = g_stats[64 + tid] * inv_cnt - mu * mu;
        float scv = gam[tid] * rsqrtf(var + 1e-5f);
        scS[tid] = scv;
        shS[tid] = beta[tid] - mu * scv;
        obsS[tid] = ob[tid];
    }
    if (tid < 128)
        dvS[tid] = g_deg[b * 1024 + (tid >> 1) * 16 + n * 2 + (tid & 1)];
    for (int i = tid; i < 1024; i += 256) {
        ((float4*)(smc + F2_OW))[i] = ((const float4*)owt)[i];
        ((float4*)(smc + F2_GW))[i] = ((const float4*)gwt)[i];
    }
    __syncthreads();

    const float4* t4 = (const float4*)tmp;
    for (int i = tid; i < 2048; i += 256) {
        int y = i >> 4, q = i & 15;
        float4 v = t4[((long)(b * 128 + y) * 8 + n) * 16 + q];
        float4 sc4 = *(const float4*)&scS[q * 4];
        float4 sh4 = *(const float4*)&shS[q * 4];
        float4 r;
        r.x = fmaxf(0.f, fmaf(v.x, sc4.x, sh4.x));
        r.y = fmaxf(0.f, fmaf(v.y, sc4.y, sh4.y));
        r.z = fmaxf(0.f, fmaf(v.z, sc4.z, sh4.z));
        r.w = fmaxf(0.f, fmaf(v.w, sc4.w, sh4.w));
        int off = y * 128 + q * 8;
        int sw = off ^ ((off >> 3) & 0x70);
        split_store(smc + F2_AH, smc + F2_AL, sw, r);
    }
    __syncthreads();

    int g = lane >> 2, tig = lane & 3;
    int m0 = wid * 16;

    float acc[8][4];
    #pragma unroll
    for (int s = 0; s < 8; s++)
        #pragma unroll
        for (int j = 0; j < 4; j++) acc[s][j] = 0.f;
    mma_3split_64(acc, sb, F2_AH, F2_AL, F2_OW, m0, lane);
    __syncthreads();

    int th = (m0 >= 64) ? 1 : 0;
    int tp0 = (m0 + g) & 63;
    #pragma unroll
    for (int s = 0; s < 8; s++) {
        int c2 = s * 8 + tig * 2;
        float o0 = obsS[c2], o1 = obsS[c2 + 1];
        int zr0 = 2 * c2 + th, zr1 = 2 * (c2 + 1) + th;
        float v00 = tanh_ap(acc[s][0] + o0);
        float v01 = tanh_ap(acc[s][1] + o1);
        float v10 = tanh_ap(acc[s][2] + o0);
        float v11 = tanh_ap(acc[s][3] + o1);
        int o00 = zr0 * 128 + tp0 * 2;       o00 ^= ((o00 >> 3) & 0x70);
        int o01 = zr1 * 128 + tp0 * 2;       o01 ^= ((o01 >> 3) & 0x70);
        int o10 = zr0 * 128 + (tp0 + 8) * 2; o10 ^= ((o10 >> 3) & 0x70);
        int o11 = zr1 * 128 + (tp0 + 8) * 2; o11 ^= ((o11 >> 3) & 0x70);
        split_store1(smc + F2_AH, smc + F2_AL, o00, v00);
        split_store1(smc + F2_AH, smc + F2_AL, o01, v01);
        split_store1(smc + F2_AH, smc + F2_AL, o10, v10);
        split_store1(smc + F2_AH, smc + F2_AL, o11, v11);
    }
    __syncthreads();

    float acc2[8][4];
    #pragma unroll
    for (int s = 0; s < 8; s++)
        #pragma unroll
        for (int j = 0; j < 4; j++) acc2[s][j] = 0.f;
    mma_3split_64(acc2, sb, F2_AH, F2_AL, F2_GW, m0, lane);
    __syncthreads();

    float* stgF = (float*)smc;
    {
        int zr0 = m0 + g, zr1 = m0 + g + 8;
        float dv0 = dvS[zr0], dv1 = dvS[zr1];
        #pragma unroll
        for (int s = 0; s < 8; s++) {
            int col = s * 8 + tig * 2;
            *(float2*)&stgF[zr0 * 68 + col] = make_float2(acc2[s][0] * dv0, acc2[s][1] * dv0);
            *(float2*)&stgF[zr1 * 68 + col] = make_float2(acc2[s][2] * dv1, acc2[s][3] * dv1);
        }
    }
    __syncthreads();
    float4* o4 = (float4*)hs2;
    long base = (long)b * 1024 + n * 2;
    #pragma unroll
    for (int jj = 0; jj < 8; jj++) {
        int idx = jj * 256 + tid;
        int zr = idx >> 4, q = idx & 15;
        long r2 = base + (zr >> 1) * 16 + (zr & 1);
        o4[r2 * 16 + q] = *(const float4*)&stgF[zr * 68 + q * 4];
    }
}

// ---------------- layer-2 final: bn->relu->1x1->tanh->regression reduce ------------
#define FM_AH 0
#define FM_AL 16384
#define FM_W  32768
#define FM_MISC 49152
#define FM_SRED (FM_MISC + 768)
#define FM_SMEM 50176

__global__ void __launch_bounds__(256, 2)
fused_final_kernel(const float* __restrict__ tmp, const __nv_bfloat16* __restrict__ wt,
                   const float* __restrict__ ob, const float* __restrict__ gam,
                   const float* __restrict__ beta, float* __restrict__ z, int statOff) {
    extern __shared__ char smc[];
    unsigned sb = smem_u32(smc);
    int tid = threadIdx.x;
    int wid = tid >> 5, lane = tid & 31;
    int row0 = blockIdx.x * 128;

    float* scS = (float*)(smc + FM_MISC);
    float* shS = scS + 64;
    float* obsS = scS + 128;
    float* sred = (float*)(smc + FM_SRED);

    if (tid < 64) {
        const float inv_cnt = 1.0f / 131072.0f;
        float mu = g_stats[statOff + tid] * inv_cnt;
        float var = g_stats[statOff + 64 + tid] * inv_cnt - mu * mu;
        float scv = gam[tid] * rsqrtf(var + 1e-5f);
        scS[tid] = scv;
        shS[tid] = beta[tid] - mu * scv;
        obsS[tid] = ob[tid];
        sred[tid] = 0.f;
    }
    for (int i = tid; i < 1024; i += 256)
        ((float4*)(smc + FM_W))[i] = ((const float4*)wt)[i];
    __syncthreads();

    const float4* t4 = (const float4*)tmp;
    for (int i = tid; i < 2048; i += 256) {
        int y = i >> 4, q = i & 15;
        float4 v = t4[(long)(row0 + y) * 16 + q];
        float4 sc4 = *(const float4*)&scS[q * 4];
        float4 sh4 = *(const float4*)&shS[q * 4];
        float4 r;
        r.x = fmaxf(0.f, fmaf(v.x, sc4.x, sh4.x));
        r.y = fmaxf(0.f, fmaf(v.y, sc4.y, sh4.y));
        r.z = fmaxf(0.f, fmaf(v.z, sc4.z, sh4.z));
        r.w = fmaxf(0.f, fmaf(v.w, sc4.w, sh4.w));
        int off = y * 128 + q * 8;
        int sw = off ^ ((off >> 3) & 0x70);
        split_store(smc + FM_AH, smc + FM_AL, sw, r);
    }
    __syncthreads();

    int g = lane >> 2, tig = lane & 3;
    int m0 = wid * 16;

    float acc[8][4];
    #pragma unroll
    for (int s = 0; s < 8; s++)
        #pragma unroll
        for (int j = 0; j < 4; j++) acc[s][j] = 0.f;
    mma_3split_64(acc, sb, FM_AH, FM_AL, FM_W, m0, lane);

    int bq = row0 >> 10;
    int t0 = ((row0 + m0) >> 3) & 127;

    float w0 = g_wbar[t0 & 63] * 0.0078125f;
    float w1 = g_wbar[(t0 + 1) & 63] * 0.0078125f;
    float s0 = 0.f, s1 = 0.f;
    #pragma unroll
    for (int s = 0; s < 8; s++) {
        int c2 = s * 8 + tig * 2;
        float o0 = obsS[c2], o1 = obsS[c2 + 1];
        s0 += tanh_ap(acc[s][0] + o0) + tanh_ap(acc[s][1] + o1);
        s1 += tanh_ap(acc[s][2] + o0) + tanh_ap(acc[s][3] + o1);
    }
    float part = w0 * s0 + w1 * s1;
    part += __shfl_xor_sync(0xffffffffu, part, 1);
    part += __shfl_xor_sync(0xffffffffu, part, 2);
    part += __shfl_xor_sync(0xffffffffu, part, 16);
    int th = (t0 >> 6) & 1;
    if (tig == 0 && g < 4) {
        int idx = (2 * g + th) & 7;
        sred[idx * 8 + wid] = part;
    }
    __syncthreads();
    if (tid < 8) {
        float ssum = 0.f;
        #pragma unroll
        for (int w = 0; w < 8; w++) ssum += sred[tid * 8 + w];
        atomicAdd(&z[bq * 8 + tid], ssum);
    }

    // re-arm next call: zero g_hist (dead here; graph-replay invariant)
    int zi = blockIdx.x * 256 + tid;
    if (zi < NROWS) g_hist[zi] = 0;
}

// ---------------- host launcher ----------------
extern "C" void kernel_launch(void* const* d_in, const int* in_sizes, int n_in,
                              void* d_out, int out_size) {
    const float* x      = (const float*)d_in[0];
    const int*   ei     = (const int*)d_in[1];
    const float* gcn1_w = (const float*)d_in[2];
    const float* gcn1_b = (const float*)d_in[3];
    const float* t1_w   = (const float*)d_in[4];
    const float* t1_b   = (const float*)d_in[5];
    const float* bn1_g  = (const float*)d_in[6];
    const float* bn1_b  = (const float*)d_in[7];
    const float* o1_w   = (const float*)d_in[8];
    const float* o1_b   = (const float*)d_in[9];
    const float* gcn2_w = (const float*)d_in[10];
    const float* gcn2_b = (const float*)d_in[11];
    const float* t2_w   = (const float*)d_in[12];
    const float* t2_b   = (const float*)d_in[13];
    const float* bn2_g  = (const float*)d_in[14];
    const float* bn2_b  = (const float*)d_in[15];
    const float* o2_w   = (const float*)d_in[16];
    const float* o2_b   = (const float*)d_in[17];
    const float* reg_w  = (const float*)d_in[18];
    const float* reg_b  = (const float*)d_in[19];
    float* out = (float*)d_out;

    const int* src = ei;
    const int* dst = ei + EDGES;

    cudaFuncSetAttribute(tconv_mma_kernel, cudaFuncAttributeMaxDynamicSharedMemorySize, TM_SMEM);
    cudaFuncSetAttribute(gemm_mma_kernel<32>, cudaFuncAttributeMaxDynamicSharedMemorySize, GM_SMEM);
    cudaFuncSetAttribute(fused_gemm2_kernel, cudaFuncAttributeMaxDynamicSharedMemorySize, F2_SMEM);
    cudaFuncSetAttribute(fused_final_kernel, cudaFuncAttributeMaxDynamicSharedMemorySize, FM_SMEM);

    float* bufA; cudaGetSymbolAddress((void**)&bufA, g_bufA);
    float* bufB; cudaGetSymbolAddress((void**)&bufB, g_bufB);
    float* bufC; cudaGetSymbolAddress((void**)&bufC, g_bufC);
    __nv_bfloat16* wt1; cudaGetSymbolAddress((void**)&wt1, g_wt1);
    __nv_bfloat16* wt2; cudaGetSymbolAddress((void**)&wt2, g_wt2);
    __nv_bfloat16* gw1; cudaGetSymbolAddress((void**)&gw1, g_gw1);
    __nv_bfloat16* gw2; cudaGetSymbolAddress((void**)&gw2, g_gw2);
    __nv_bfloat16* ow1; cudaGetSymbolAddress((void**)&ow1, g_ow1);
    __nv_bfloat16* ow2; cudaGetSymbolAddress((void**)&ow2, g_ow2);

    // sort + weight prep (g_hist was zeroed by previous call's fused_final)
    phist_kernel<<<EDGES / 256, 256>>>(dst, reg_w, reg_b, t1_w, t2_w,
                                       gcn1_w, gcn2_w, o1_w, o2_w);
    scan1_kernel<<<128, 256>>>();
    scan3_kernel<<<NROWS / 256, 256>>>(reg_b, out);
    scatter_kernel<<<EDGES / 256, 256>>>(src, dst);

    // -------- layer 1 --------
    gemm_mma_kernel<32><<<NROWS / 128, 256, GM_SMEM>>>(x, gw1, bufA);
    gather_agg_kernel<<<NROWS / 16, 256>>>(bufA, gcn1_b, bufB);
    tconv_mma_kernel<<<1024, 256, TM_SMEM>>>(bufB, wt1, t1_b, bufC, 0);
    fused_gemm2_kernel<<<1024, 256, F2_SMEM>>>(bufC, ow1, gw2, o1_b, bn1_g, bn1_b, bufA);

    // -------- layer 2 --------
    gather_agg_kernel<<<NROWS / 16, 256>>>(bufA, gcn2_b, bufB);
    tconv_mma_kernel<<<1024, 256, TM_SMEM>>>(bufB, wt2, t2_b, bufC, 128);
    fused_final_kernel<<<NROWS / 128, 256, FM_SMEM>>>(bufC, ow2, o2_b, bn2_g, bn2_b, out, 128);
}

// round 17
// speedup vs baseline: 1.2116x; 1.0248x over previous
#include <cuda_runtime.h>
#include <cuda_bf16.h>
#include <cstdint>
#include <stdint.h>
#include <math.h>

#define NROWS 131072
#define EDGES 1048576

#define PDL_WAIT()    asm volatile("griddepcontrol.wait;" ::: "memory")
#define PDL_TRIGGER() asm volatile("griddepcontrol.launch_dependents;" ::: "memory")

// ---------------- scratch (device globals) ----------------
__device__ float g_bufA[NROWS * 64];
__device__ float g_bufB[NROWS * 64];
__device__ float g_bufC[NROWS * 64];
__device__ float g_deg[NROWS];      // dinv
__device__ int   g_hist[NROWS];     // zeroed at END of pipeline (fused_final tail)
__device__ int   g_off[NROWS];
__device__ int   g_cursor[NROWS];
__device__ int   g_bsum[128];
__device__ int   g_srcs[EDGES];
__device__ float g_stats[256];      // zeroed early (scan1 tail)
__device__ float g_wbar[65];
// bf16 weight tiles, XOR-swizzled 128B rows, hi tile then lo tile
__device__ __align__(16) __nv_bfloat16 g_wt1[24576];  // tconv l1: [tap*2+split][64x64]
__device__ __align__(16) __nv_bfloat16 g_wt2[24576];  // tconv l2
__device__ __align__(16) __nv_bfloat16 g_gw1[8192];   // gcn1_w [32k x 64n]
__device__ __align__(16) __nv_bfloat16 g_gw2[8192];   // gcn2_w [64k x 64n]
__device__ __align__(16) __nv_bfloat16 g_ow1[8192];   // o1_w^T [64c x 64c2]
__device__ __align__(16) __nv_bfloat16 g_ow2[8192];   // o2_w^T

typedef unsigned long long ull;
__device__ __forceinline__ float tanh_ap(float x) {
    float y; asm("tanh.approx.f32 %0,%1;" : "=f"(y) : "f"(x)); return y;
}

// ---------------- mma.sync helpers ----------------
__device__ __forceinline__ unsigned smem_u32(const void* p) {
    unsigned a;
    asm("{ .reg .u64 t; cvta.to.shared.u64 t, %1; cvt.u32.u64 %0, t; }" : "=r"(a) : "l"(p));
    return a;
}
__device__ __forceinline__ void ldsm4(unsigned& r0, unsigned& r1, unsigned& r2, unsigned& r3,
                                      unsigned addr) {
    asm volatile("ldmatrix.sync.aligned.m8n8.x4.shared.b16 {%0,%1,%2,%3}, [%4];"
                 : "=r"(r0), "=r"(r1), "=r"(r2), "=r"(r3) : "r"(addr));
}
__device__ __forceinline__ void ldsm4t(unsigned& r0, unsigned& r1, unsigned& r2, unsigned& r3,
                                       unsigned addr) {
    asm volatile("ldmatrix.sync.aligned.m8n8.x4.trans.shared.b16 {%0,%1,%2,%3}, [%4];"
                 : "=r"(r0), "=r"(r1), "=r"(r2), "=r"(r3) : "r"(addr));
}
__device__ __forceinline__ void mma_bf16(float* c, unsigned a0, unsigned a1, unsigned a2,
                                         unsigned a3, unsigned b0, unsigned b1) {
    asm volatile(
        "mma.sync.aligned.m16n8k16.row.col.f32.bf16.bf16.f32 "
        "{%0,%1,%2,%3}, {%4,%5,%6,%7}, {%8,%9}, {%0,%1,%2,%3};"
        : "+f"(c[0]), "+f"(c[1]), "+f"(c[2]), "+f"(c[3])
        : "r"(a0), "r"(a1), "r"(a2), "r"(a3), "r"(b0), "r"(b1));
}
__device__ __forceinline__ void split_store(char* hi, char* lo, int sw, float4 v) {
    __nv_bfloat162 h01 = __floats2bfloat162_rn(v.x, v.y);
    __nv_bfloat162 h23 = __floats2bfloat162_rn(v.z, v.w);
    float lx = v.x - __bfloat162float(h01.x);
    float ly = v.y - __bfloat162float(h01.y);
    float lz = v.z - __bfloat162float(h23.x);
    float lw = v.w - __bfloat162float(h23.y);
    __nv_bfloat162 l01 = __floats2bfloat162_rn(lx, ly);
    __nv_bfloat162 l23 = __floats2bfloat162_rn(lz, lw);
    uint2 hp, lp;
    hp.x = *(unsigned*)&h01; hp.y = *(unsigned*)&h23;
    lp.x = *(unsigned*)&l01; lp.y = *(unsigned*)&l23;
    *(uint2*)(hi + sw) = hp;
    *(uint2*)(lo + sw) = lp;
}
__device__ __forceinline__ void split_store1(char* hi, char* lo, int sw, float v) {
    __nv_bfloat16 h = __float2bfloat16_rn(v);
    __nv_bfloat16 l = __float2bfloat16_rn(v - __bfloat162float(h));
    *(__nv_bfloat16*)(hi + sw) = h;
    *(__nv_bfloat16*)(lo + sw) = l;
}

// one k16 step of the 3-term bf16 split GEMM: Ah*Bh + Ah*Bl + Al*Bh
__device__ __forceinline__ void mma_3split_k16(float acc[8][4], unsigned ahRow, unsigned alRow,
                                               unsigned asw, unsigned bhTile, unsigned blTile,
                                               int k16, int arow, int lext) {
    unsigned a0, a1, a2, a3, c0, c1, c2, c3;
    unsigned kb = (((unsigned)(k16 * 32)) + lext) ^ asw;
    ldsm4(a0, a1, a2, a3, ahRow + kb);
    ldsm4(c0, c1, c2, c3, alRow + kb);
    int krow = k16 * 16 + arow;
    unsigned bro = (unsigned)(krow * 128);
    unsigned bsw = (unsigned)((krow & 7) << 4);
    #pragma unroll
    for (int nn = 0; nn < 4; nn++) {
        unsigned b0, b1, b2, b3, d0, d1, d2, d3;
        unsigned nb = (((unsigned)(nn * 32)) + lext) ^ bsw;
        ldsm4t(b0, b1, b2, b3, bhTile + bro + nb);
        ldsm4t(d0, d1, d2, d3, blTile + bro + nb);
        mma_bf16(acc[2 * nn],     a0, a1, a2, a3, b0, b1);
        mma_bf16(acc[2 * nn + 1], a0, a1, a2, a3, b2, b3);
        mma_bf16(acc[2 * nn],     a0, a1, a2, a3, d0, d1);
        mma_bf16(acc[2 * nn + 1], a0, a1, a2, a3, d2, d3);
        mma_bf16(acc[2 * nn],     c0, c1, c2, c3, b0, b1);
        mma_bf16(acc[2 * nn + 1], c0, c1, c2, c3, b2, b3);
    }
}

__device__ __forceinline__ void mma_3split_64(float acc[8][4], unsigned sb, unsigned ahOff,
                                              unsigned alOff, unsigned wOff, int m0, int lane) {
    int arow = lane & 15;
    int lext = (lane >> 4) << 4;
    int ay = m0 + arow;
    unsigned ahRow = sb + ahOff + (unsigned)(ay * 128);
    unsigned alRow = sb + alOff + (unsigned)(ay * 128);
    unsigned asw = (unsigned)((ay & 7) << 4);
    #pragma unroll
    for (int k16 = 0; k16 < 4; k16++)
        mma_3split_k16(acc, ahRow, alRow, asw, sb + wOff, sb + wOff + 8192u, k16, arow, lext);
}

// ---------------- phist: hist atomics + weight prep (merged prologue) ----------------
__global__ void phist_kernel(const int* __restrict__ dst,
                             const float* __restrict__ rw, const float* __restrict__ rb,
                             const float* __restrict__ t1w, const float* __restrict__ t2w,
                             const float* __restrict__ g1w, const float* __restrict__ g2w,
                             const float* __restrict__ o1w, const float* __restrict__ o2w) {
    int i = blockIdx.x * blockDim.x + threadIdx.x;    // 0 .. EDGES-1
    atomicAdd(&g_hist[dst[i]], 1);

    if (i < 12288) {
        int k = i >> 12;
        int r = i & 4095;
        int c2 = r >> 6, c = r & 63;
        int off = c * 128 + c2 * 2;
        int sw = off ^ ((off >> 3) & 0x70);
        int idx = sw >> 1;
        float w1 = t1w[(c2 * 64 + c) * 3 + k];
        float w2 = t2w[(c2 * 64 + c) * 3 + k];
        __nv_bfloat16 h1 = __float2bfloat16_rn(w1);
        __nv_bfloat16 h2 = __float2bfloat16_rn(w2);
        g_wt1[(k * 2 + 0) * 4096 + idx] = h1;
        g_wt1[(k * 2 + 1) * 4096 + idx] = __float2bfloat16_rn(w1 - __bfloat162float(h1));
        g_wt2[(k * 2 + 0) * 4096 + idx] = h2;
        g_wt2[(k * 2 + 1) * 4096 + idx] = __float2bfloat16_rn(w2 - __bfloat162float(h2));
    } else if (i < 16384) {
        int j = i - 12288;
        int k = j >> 6, n = j & 63;
        int off = k * 128 + n * 2;
        int sw = off ^ ((off >> 3) & 0x70);
        int idx = sw >> 1;
        float w = g2w[k * 64 + n];
        __nv_bfloat16 h = __float2bfloat16_rn(w);
        g_gw2[idx] = h;
        g_gw2[4096 + idx] = __float2bfloat16_rn(w - __bfloat162float(h));
    } else if (i < 20480) {
        int j = i - 16384;
        int c = j >> 6, c2 = j & 63;
        int off = c * 128 + c2 * 2;
        int sw = off ^ ((off >> 3) & 0x70);
        int idx = sw >> 1;
        float w = o1w[c2 * 64 + c];
        __nv_bfloat16 h = __float2bfloat16_rn(w);
        g_ow1[idx] = h;
        g_ow1[4096 + idx] = __float2bfloat16_rn(w - __bfloat162float(h));
    } else if (i < 24576) {
        int j = i - 20480;
        int c = j >> 6, c2 = j & 63;
        int off = c * 128 + c2 * 2;
        int sw = off ^ ((off >> 3) & 0x70);
        int idx = sw >> 1;
        float w = o2w[c2 * 64 + c];
        __nv_bfloat16 h = __float2bfloat16_rn(w);
        g_ow2[idx] = h;
        g_ow2[4096 + idx] = __float2bfloat16_rn(w - __bfloat162float(h));
    } else if (i < 26624) {
        int j = i - 24576;
        int k = j >> 6, n = j & 63;
        int off = k * 128 + n * 2;
        int sw = off ^ ((off >> 3) & 0x70);
        int idx = sw >> 1;
        float w = g1w[k * 64 + n];
        __nv_bfloat16 h = __float2bfloat16_rn(w);
        g_gw1[idx] = h;
        g_gw1[4096 + idx] = __float2bfloat16_rn(w - __bfloat162float(h));
    }
    if (i < 64) {
        float s = 0.f;
        #pragma unroll
        for (int j = 0; j < 8; j++) s += rw[i * 8 + j];
        g_wbar[i] = s * 0.125f;
    }
    if (i == 64) {
        float s = 0.f;
        #pragma unroll
        for (int j = 0; j < 8; j++) s += rb[j];
        g_wbar[64] = s * 0.125f;
    }
    PDL_TRIGGER();
}

__global__ void scan1_kernel() {
    PDL_WAIT();
    __shared__ int sh[256];
    int tid = threadIdx.x;
    int base = blockIdx.x * 1024 + tid * 4;
    int4 v = *(const int4*)&g_hist[base];
    int s0 = v.x, s1 = s0 + v.y, s2 = s1 + v.z, s3 = s2 + v.w;
    sh[tid] = s3;
    __syncthreads();
    #pragma unroll
    for (int o = 1; o < 256; o <<= 1) {
        int t = (tid >= o) ? sh[tid - o] : 0;
        __syncthreads();
        sh[tid] += t;
        __syncthreads();
    }
    int excl = tid ? sh[tid - 1] : 0;
    int4 w = make_int4(excl, excl + s0, excl + s1, excl + s2);
    *(int4*)&g_off[base] = w;
    if (tid == 255) g_bsum[blockIdx.x] = sh[255];
    int gi = blockIdx.x * 256 + tid;
    if (gi < 256) g_stats[gi] = 0.0f;
    PDL_TRIGGER();
}

// scan3: local re-scan of the 128 segment sums + dinv/cursor/out-init
__global__ void scan3_kernel(const float* __restrict__ rb, float* __restrict__ out) {
    PDL_WAIT();
    __shared__ int bs[128];
    int tid = threadIdx.x;
    if (tid < 128) bs[tid] = g_bsum[tid];
    __syncthreads();
    #pragma unroll
    for (int o = 1; o < 128; o <<= 1) {
        int t = (tid < 128 && tid >= o) ? bs[tid - o] : 0;
        __syncthreads();
        if (tid < 128) bs[tid] += t;
        __syncthreads();
    }
    int i = blockIdx.x * blockDim.x + tid;
    if (i < NROWS) {
        int seg = i >> 10;
        int o = g_off[i] + (seg ? bs[seg - 1] : 0);
        g_off[i] = o;
        g_cursor[i] = o;
        g_deg[i] = rsqrtf((float)g_hist[i] + 1.0f);
    }
    if (i < 1024) {
        float s = 0.f;
        #pragma unroll
        for (int j = 0; j < 8; j++) s += rb[j];
        out[i] = s * 0.125f;
    }
    PDL_TRIGGER();
}

__global__ void scatter_kernel(const int* __restrict__ src, const int* __restrict__ dst) {
    int e = blockIdx.x * blockDim.x + threadIdx.x;
    int s = src[e];                 // pre-wait: inputs only
    int d = dst[e];
    PDL_WAIT();
    int pos = atomicAdd(&g_cursor[d], 1);
    g_srcs[pos] = s;
    PDL_TRIGGER();
}

// ---------------- GEMM hs = (A@W)*dinv via mma.sync (layer 1 input) ----------------
#define GM_AH 0
#define GM_AL 16384
#define GM_W  32768
#define GM_SMEM 49152

template <int K>
__global__ void __launch_bounds__(256, 2)
gemm_mma_kernel(const float* __restrict__ A, const __nv_bfloat16* __restrict__ wt,
                float* __restrict__ hs) {
    extern __shared__ char smc[];
    unsigned sb = smem_u32(smc);
    int tid = threadIdx.x;
    int wid = tid >> 5, lane = tid & 31;
    int row0 = blockIdx.x * 128;

    // pre-wait: A tile load + split (x is a harness input, independent of sort chain)
    constexpr int QR = K / 4;
    const float4* a4 = (const float4*)A;
    for (int i = tid; i < 128 * QR; i += 256) {
        int y = i / QR, q = i - y * QR;
        float4 v = a4[(long)(row0 + y) * QR + q];
        int off = y * 128 + q * 8;
        int sw = off ^ ((off >> 3) & 0x70);
        split_store(smc + GM_AH, smc + GM_AL, sw, v);
    }
    PDL_WAIT();
    for (int i = tid; i < 1024; i += 256)
        ((float4*)(smc + GM_W))[i] = ((const float4*)wt)[i];
    __syncthreads();

    int g = lane >> 2, tig = lane & 3;
    int m0 = wid * 16;
    int arow = lane & 15;
    int lext = (lane >> 4) << 4;

    float acc[8][4];
    #pragma unroll
    for (int s = 0; s < 8; s++)
        #pragma unroll
        for (int j = 0; j < 4; j++) acc[s][j] = 0.f;

    {
        int ay = m0 + arow;
        unsigned ahRow = sb + GM_AH + (unsigned)(ay * 128);
        unsigned alRow = sb + GM_AL + (unsigned)(ay * 128);
        unsigned asw = (unsigned)((ay & 7) << 4);
        #pragma unroll
        for (int k16 = 0; k16 < K / 16; k16++)
            mma_3split_k16(acc, ahRow, alRow, asw, sb + GM_W, sb + GM_W + 8192u,
                           k16, arow, lext);
    }
    __syncthreads();
    PDL_TRIGGER();

    float* stg = (float*)smc;       // [128][68]
    int r0 = row0 + m0 + g, r1 = r0 + 8;
    float dv0 = g_deg[r0], dv1 = g_deg[r1];
    #pragma unroll
    for (int s = 0; s < 8; s++) {
        int col = s * 8 + tig * 2;
        float2 p0 = make_float2(acc[s][0] * dv0, acc[s][1] * dv0);
        float2 p1 = make_float2(acc[s][2] * dv1, acc[s][3] * dv1);
        *(float2*)&stg[(m0 + g) * 68 + col] = p0;
        *(float2*)&stg[(m0 + g + 8) * 68 + col] = p1;
    }
    __syncthreads();
    float4* o4 = (float4*)hs;
    #pragma unroll
    for (int jj = 0; jj < 8; jj++) {
        int idx = jj * 256 + tid;
        int mm = idx >> 4, q = idx & 15;
        o4[(long)(row0 + mm) * 16 + q] = *(const float4*)&stg[mm * 68 + q * 4];
    }
}

// ---------------- sorted gather aggregation (atomic-free, standalone) ----------------
__global__ void gather_agg_kernel(const float* __restrict__ hs, const float* __restrict__ bias,
                                  float* __restrict__ agg) {
    PDL_WAIT();
    int tid = threadIdx.x;              // 256
    int r = blockIdx.x * 16 + (tid >> 4);
    int q = tid & 15;
    int off = __ldg(&g_off[r]);
    int cnt = __ldg(&g_hist[r]);
    float dv = g_deg[r];
    const float4* h4 = (const float4*)hs;

    float4 acc = __ldg(&h4[(long)r * 16 + q]);
    int i = 0;
    for (; i + 2 <= cnt; i += 2) {
        int s0 = __ldg(&g_srcs[off + i]);
        int s1 = __ldg(&g_srcs[off + i + 1]);
        float4 v0 = __ldg(&h4[(long)s0 * 16 + q]);
        float4 v1 = __ldg(&h4[(long)s1 * 16 + q]);
        acc.x += v0.x + v1.x; acc.y += v0.y + v1.y;
        acc.z += v0.z + v1.z; acc.w += v0.w + v1.w;
    }
    if (i < cnt) {
        int s0 = __ldg(&g_srcs[off + i]);
        float4 v0 = __ldg(&h4[(long)s0 * 16 + q]);
        acc.x += v0.x; acc.y += v0.y; acc.z += v0.z; acc.w += v0.w;
    }
    float4 b = __ldg(&((const float4*)bias)[q]);
    float4 o = make_float4(fmaf(acc.x, dv, b.x), fmaf(acc.y, dv, b.y),
                           fmaf(acc.z, dv, b.z), fmaf(acc.w, dv, b.w));
    ((float4*)agg)[(long)r * 16 + q] = o;
    PDL_TRIGGER();
}

// ---------------- temporal (1,3) conv via mma.sync ----------------
#define TM_A_HI 0
#define TM_A_LO 18432
#define TM_B    36864
#define TM_BIAS 86016
#define TM_PART 86272
#define TM_SMEM 88320

__global__ void __launch_bounds__(256, 2)
tconv_mma_kernel(const float* __restrict__ in, const __nv_bfloat16* __restrict__ wt,
                 const float* __restrict__ tb, float* __restrict__ out, int statOff) {
    extern __shared__ char smc[];
    unsigned sb = smem_u32(smc);
    int tid = threadIdx.x;
    int wid = tid >> 5;
    int lane = tid & 31;
    int p = blockIdx.x;
    int b = p >> 3;
    int mt = p & 7;

    if (tid < 64) ((float*)(smc + TM_BIAS))[tid] = tb[tid];   // pre-wait (input)
    PDL_WAIT();
    for (int i = tid; i < 3072; i += 256)
        ((float4*)(smc + TM_B))[i] = ((const float4*)wt)[i];

    const float4* in4 = (const float4*)in;
    for (int i = tid; i < 2304; i += 256) {
        int y = i >> 4, q = i & 15;
        int rr = mt * 128 + y - 8;
        float4 v = make_float4(0.f, 0.f, 0.f, 0.f);
        if (rr >= 0 && rr < 1024) v = in4[(long)(b * 1024 + rr) * 16 + q];
        int off = y * 128 + q * 8;
        int sw = off ^ ((off >> 3) & 0x70);
        split_store(smc + TM_A_HI, smc + TM_A_LO, sw, v);
    }
    __syncthreads();

    int g = lane >> 2, tig = lane & 3;
    int m0 = wid * 16;
    int arow = lane & 15;
    int lext = (lane >> 4) << 4;

    float acc[8][4];
    #pragma unroll
    for (int s = 0; s < 8; s++)
        #pragma unroll
        for (int j = 0; j < 4; j++) acc[s][j] = 0.f;

    #pragma unroll 1
    for (int tap = 0; tap < 3; tap++) {
        int ay = tap * 8 + m0 + arow;
        unsigned ahRow = sb + TM_A_HI + (unsigned)(ay * 128);
        unsigned alRow = sb + TM_A_LO + (unsigned)(ay * 128);
        unsigned asw = (unsigned)((ay & 7) << 4);
        unsigned bh = sb + TM_B + (unsigned)(tap * 2) * 8192u;
        #pragma unroll
        for (int k16 = 0; k16 < 4; k16++)
            mma_3split_k16(acc, ahRow, alRow, asw, bh, bh + 8192u, k16, arow, lext);
    }
    __syncthreads();
    PDL_TRIGGER();

    float* stg = (float*)smc;
    const float* biasS = (const float*)(smc + TM_BIAS);
    #pragma unroll
    for (int s = 0; s < 8; s++) {
        int col = s * 8 + tig * 2;
        float b0v = biasS[col], b1v = biasS[col + 1];
        int r0 = m0 + g, r1 = m0 + g + 8;
        stg[r0 * 68 + col]     = acc[s][0] + b0v;
        stg[r0 * 68 + col + 1] = acc[s][1] + b1v;
        stg[r1 * 68 + col]     = acc[s][2] + b0v;
        stg[r1 * 68 + col + 1] = acc[s][3] + b1v;
    }
    __syncthreads();

    {
        int g2 = tid >> 6, c2 = tid & 63;
        float s = 0.f, qq = 0.f;
        #pragma unroll 8
        for (int i2 = 0; i2 < 32; i2++) {
            float v = stg[(g2 * 32 + i2) * 68 + c2];
            s += v; qq = fmaf(v, v, qq);
        }
        float* ps = (float*)(smc + TM_PART);
        ps[g2 * 64 + c2] = s;
        ps[256 + g2 * 64 + c2] = qq;
    }
    __syncthreads();
    {
        const float* ps = (const float*)(smc + TM_PART);
        if (tid < 64)
            atomicAdd(&g_stats[statOff + tid], ps[tid] + ps[64 + tid] + ps[128 + tid] + ps[192 + tid]);
        else if (tid < 128) {
            int c = tid - 64;
            atomicAdd(&g_stats[statOff + 64 + c],
                      ps[256 + c] + ps[320 + c] + ps[384 + c] + ps[448 + c]);
        }
    }

    float4* out4 = (float4*)out;
    long rb16 = (long)(b * 1024 + mt * 128) * 16;
    #pragma unroll
    for (int jj = 0; jj < 8; jj++) {
        int idx = jj * 256 + tid;
        int mm = idx >> 4, q = idx & 15;
        out4[rb16 + mm * 16 + q] = *(const float4*)&stg[mm * 68 + q * 4];
    }
}

// ---------------- layer-1 epilogue fused with layer-2 GEMM ----------------
#define F2_AH   0
#define F2_AL   16384
#define F2_OW   32768
#define F2_GW   49152
#define F2_MISC 65536
#define F2_SMEM (F2_MISC + 1280)           // 66816

__global__ void __launch_bounds__(256, 2)
fused_gemm2_kernel(const float* __restrict__ tmp, const __nv_bfloat16* __restrict__ owt,
                   const __nv_bfloat16* __restrict__ gwt, const float* __restrict__ ob,
                   const float* __restrict__ gam, const float* __restrict__ beta,
                   float* __restrict__ hs2) {
    extern __shared__ char smc[];
    unsigned sb = smem_u32(smc);
    int tid = threadIdx.x;
    int wid = tid >> 5, lane = tid & 31;
    int p = blockIdx.x;                 // 1024
    int b = p >> 3, n = p & 7;

    float* scS = (float*)(smc + F2_MISC);
    float* shS = scS + 64;
    float* obsS = scS + 128;
    float* dvS = scS + 192;             // [128]

    if (tid < 64) obsS[tid] = ob[tid];  // pre-wait (input)
    PDL_WAIT();
    if (tid < 64) {
        const float inv_cnt = 1.0f / 131072.0f;
        float mu = g_stats[tid] * inv_cnt;
        float var = g_stats[64 + tid] * inv_cnt - mu * mu;
        float scv = gam[tid] * rsqrtf(var + 1e-5f);
        scS[tid] = scv;
        shS[tid] = beta[tid] - mu * scv;
    }
    if (tid < 128)
        dvS[tid] = g_deg[b * 1024 + (tid >> 1) * 16 + n * 2 + (tid & 1)];
    for (int i = tid; i < 1024; i += 256) {
        ((float4*)(smc + F2_OW))[i] = ((const float4*)owt)[i];
        ((float4*)(smc + F2_GW))[i] = ((const float4*)gwt)[i];
    }
    __syncthreads();

    const float4* t4 = (const float4*)tmp;
    for (int i = tid; i < 2048; i += 256) {
        int y = i >> 4, q = i & 15;
        float4 v = t4[((long)(b * 128 + y) * 8 + n) * 16 + q];
        float4 sc4 = *(const float4*)&scS[q * 4];
        float4 sh4 = *(const float4*)&shS[q * 4];
        float4 r;
        r.x = fmaxf(0.f, fmaf(v.x, sc4.x, sh4.x));
        r.y = fmaxf(0.f, fmaf(v.y, sc4.y, sh4.y));
        r.z = fmaxf(0.f, fmaf(v.z, sc4.z, sh4.z));
        r.w = fmaxf(0.f, fmaf(v.w, sc4.w, sh4.w));
        int off = y * 128 + q * 8;
        int sw = off ^ ((off >> 3) & 0x70);
        split_store(smc + F2_AH, smc + F2_AL, sw, r);
    }
    __syncthreads();

    int g = lane >> 2, tig = lane & 3;
    int m0 = wid * 16;

    float acc[8][4];
    #pragma unroll
    for (int s = 0; s < 8; s++)
        #pragma unroll
        for (int j = 0; j < 4; j++) acc[s][j] = 0.f;
    mma_3split_64(acc, sb, F2_AH, F2_AL, F2_OW, m0, lane);
    __syncthreads();

    int th = (m0 >= 64) ? 1 : 0;
    int tp0 = (m0 + g) & 63;
    #pragma unroll
    for (int s = 0; s < 8; s++) {
        int c2 = s * 8 + tig * 2;
        float o0 = obsS[c2], o1 = obsS[c2 + 1];
        int zr0 = 2 * c2 + th, zr1 = 2 * (c2 + 1) + th;
        float v00 = tanh_ap(acc[s][0] + o0);
        float v01 = tanh_ap(acc[s][1] + o1);
        float v10 = tanh_ap(acc[s][2] + o0);
        float v11 = tanh_ap(acc[s][3] + o1);
        int o00 = zr0 * 128 + tp0 * 2;       o00 ^= ((o00 >> 3) & 0x70);
        int o01 = zr1 * 128 + tp0 * 2;       o01 ^= ((o01 >> 3) & 0x70);
        int o10 = zr0 * 128 + (tp0 + 8) * 2; o10 ^= ((o10 >> 3) & 0x70);
        int o11 = zr1 * 128 + (tp0 + 8) * 2; o11 ^= ((o11 >> 3) & 0x70);
        split_store1(smc + F2_AH, smc + F2_AL, o00, v00);
        split_store1(smc + F2_AH, smc + F2_AL, o01, v01);
        split_store1(smc + F2_AH, smc + F2_AL, o10, v10);
        split_store1(smc + F2_AH, smc + F2_AL, o11, v11);
    }
    __syncthreads();

    float acc2[8][4];
    #pragma unroll
    for (int s = 0; s < 8; s++)
        #pragma unroll
        for (int j = 0; j < 4; j++) acc2[s][j] = 0.f;
    mma_3split_64(acc2, sb, F2_AH, F2_AL, F2_GW, m0, lane);
    __syncthreads();
    PDL_TRIGGER();

    float* stgF = (float*)smc;
    {
        int zr0 = m0 + g, zr1 = m0 + g + 8;
        float dv0 = dvS[zr0], dv1 = dvS[zr1];
        #pragma unroll
        for (int s = 0; s < 8; s++) {
            int col = s * 8 + tig * 2;
            *(float2*)&stgF[zr0 * 68 + col] = make_float2(acc2[s][0] * dv0, acc2[s][1] * dv0);
            *(float2*)&stgF[zr1 * 68 + col] = make_float2(acc2[s][2] * dv1, acc2[s][3] * dv1);
        }
    }
    __syncthreads();
    float4* o4 = (float4*)hs2;
    long base = (long)b * 1024 + n * 2;
    #pragma unroll
    for (int jj = 0; jj < 8; jj++) {
        int idx = jj * 256 + tid;
        int zr = idx >> 4, q = idx & 15;
        long r2 = base + (zr >> 1) * 16 + (zr & 1);
        o4[r2 * 16 + q] = *(const float4*)&stgF[zr * 68 + q * 4];
    }
}

// ---------------- layer-2 final: bn->relu->1x1->tanh->regression reduce ------------
#define FM_AH 0
#define FM_AL 16384
#define FM_W  32768
#define FM_MISC 49152
#define FM_SRED (FM_MISC + 768)
#define FM_SMEM 50176

__global__ void __launch_bounds__(256, 2)
fused_final_kernel(const float* __restrict__ tmp, const __nv_bfloat16* __restrict__ wt,
                   const float* __restrict__ ob, const float* __restrict__ gam,
                   const float* __restrict__ beta, float* __restrict__ z, int statOff) {
    extern __shared__ char smc[];
    unsigned sb = smem_u32(smc);
    int tid = threadIdx.x;
    int wid = tid >> 5, lane = tid & 31;
    int row0 = blockIdx.x * 128;

    float* scS = (float*)(smc + FM_MISC);
    float* shS = scS + 64;
    float* obsS = scS + 128;
    float* sred = (float*)(smc + FM_SRED);

    if (tid < 64) { obsS[tid] = ob[tid]; sred[tid] = 0.f; }   // pre-wait
    PDL_WAIT();
    if (tid < 64) {
        const float inv_cnt = 1.0f / 131072.0f;
        float mu = g_stats[statOff + tid] * inv_cnt;
        float var = g_stats[statOff + 64 + tid] * inv_cnt - mu * mu;
        float scv = gam[tid] * rsqrtf(var + 1e-5f);
        scS[tid] = scv;
        shS[tid] = beta[tid] - mu * scv;
    }
    for (int i = tid; i < 1024; i += 256)
        ((float4*)(smc + FM_W))[i] = ((const float4*)wt)[i];
    __syncthreads();

    const float4* t4 = (const float4*)tmp;
    for (int i = tid; i < 2048; i += 256) {
        int y = i >> 4, q = i & 15;
        float4 v = t4[(long)(row0 + y) * 16 + q];
        float4 sc4 = *(const float4*)&scS[q * 4];
        float4 sh4 = *(const float4*)&shS[q * 4];
        float4 r;
        r.x = fmaxf(0.f, fmaf(v.x, sc4.x, sh4.x));
        r.y = fmaxf(0.f, fmaf(v.y, sc4.y, sh4.y));
        r.z = fmaxf(0.f, fmaf(v.z, sc4.z, sh4.z));
        r.w = fmaxf(0.f, fmaf(v.w, sc4.w, sh4.w));
        int off = y * 128 + q * 8;
        int sw = off ^ ((off >> 3) & 0x70);
        split_store(smc + FM_AH, smc + FM_AL, sw, r);
    }
    __syncthreads();

    int g = lane >> 2, tig = lane & 3;
    int m0 = wid * 16;

    float acc[8][4];
    #pragma unroll
    for (int s = 0; s < 8; s++)
        #pragma unroll
        for (int j = 0; j < 4; j++) acc[s][j] = 0.f;
    mma_3split_64(acc, sb, FM_AH, FM_AL, FM_W, m0, lane);

    int bq = row0 >> 10;
    int t0 = ((row0 + m0) >> 3) & 127;

    float w0 = g_wbar[t0 & 63] * 0.0078125f;
    float w1 = g_wbar[(t0 + 1) & 63] * 0.0078125f;
    float s0 = 0.f, s1 = 0.f;
    #pragma unroll
    for (int s = 0; s < 8; s++) {
        int c2 = s * 8 + tig * 2;
        float o0 = obsS[c2], o1 = obsS[c2 + 1];
        s0 += tanh_ap(acc[s][0] + o0) + tanh_ap(acc[s][1] + o1);
        s1 += tanh_ap(acc[s][2] + o0) + tanh_ap(acc[s][3] + o1);
    }
    float part = w0 * s0 + w1 * s1;
    part += __shfl_xor_sync(0xffffffffu, part, 1);
    part += __shfl_xor_sync(0xffffffffu, part, 2);
    part += __shfl_xor_sync(0xffffffffu, part, 16);
    int th = (t0 >> 6) & 1;
    if (tig == 0 && g < 4) {
        int idx = (2 * g + th) & 7;
        sred[idx * 8 + wid] = part;
    }
    __syncthreads();
    if (tid < 8) {
        float ssum = 0.f;
        #pragma unroll
        for (int w = 0; w < 8; w++) ssum += sred[tid * 8 + w];
        atomicAdd(&z[bq * 8 + tid], ssum);
    }

    // re-arm next call: zero g_hist (dead here; graph-replay invariant)
    int zi = blockIdx.x * 256 + tid;
    if (zi < NROWS) g_hist[zi] = 0;
}

// ---------------- host PDL launch helper ----------------
template <typename F, typename... Args>
static void launchPDL(F kern, dim3 grid, dim3 block, size_t smem, Args... args) {
    cudaLaunchConfig_t cfg = {};
    cfg.gridDim = grid;
    cfg.blockDim = block;
    cfg.dynamicSmemBytes = smem;
    cfg.stream = 0;
    cudaLaunchAttribute at[1];
    at[0].id = cudaLaunchAttributeProgrammaticStreamSerialization;
    at[0].val.programmaticStreamSerializationAllowed = 1;
    cfg.attrs = at;
    cfg.numAttrs = 1;
    cudaLaunchKernelEx(&cfg, kern, args...);
}

// ---------------- host launcher ----------------
extern "C" void kernel_launch(void* const* d_in, const int* in_sizes, int n_in,
                              void* d_out, int out_size) {
    const float* x      = (const float*)d_in[0];
    const int*   ei     = (const int*)d_in[1];
    const float* gcn1_w = (const float*)d_in[2];
    const float* gcn1_b = (const float*)d_in[3];
    const float* t1_w   = (const float*)d_in[4];
    const float* t1_b   = (const float*)d_in[5];
    const float* bn1_g  = (const float*)d_in[6];
    const float* bn1_b  = (const float*)d_in[7];
    const float* o1_w   = (const float*)d_in[8];
    const float* o1_b   = (const float*)d_in[9];
    const float* gcn2_w = (const float*)d_in[10];
    const float* gcn2_b = (const float*)d_in[11];
    const float* t2_w   = (const float*)d_in[12];
    const float* t2_b   = (const float*)d_in[13];
    const float* bn2_g  = (const float*)d_in[14];
    const float* bn2_b  = (const float*)d_in[15];
    const float* o2_w   = (const float*)d_in[16];
    const float* o2_b   = (const float*)d_in[17];
    const float* reg_w  = (const float*)d_in[18];
    const float* reg_b  = (const float*)d_in[19];
    float* out = (float*)d_out;

    const int* src = ei;
    const int* dst = ei + EDGES;

    cudaFuncSetAttribute(tconv_mma_kernel, cudaFuncAttributeMaxDynamicSharedMemorySize, TM_SMEM);
    cudaFuncSetAttribute(gemm_mma_kernel<32>, cudaFuncAttributeMaxDynamicSharedMemorySize, GM_SMEM);
    cudaFuncSetAttribute(fused_gemm2_kernel, cudaFuncAttributeMaxDynamicSharedMemorySize, F2_SMEM);
    cudaFuncSetAttribute(fused_final_kernel, cudaFuncAttributeMaxDynamicSharedMemorySize, FM_SMEM);

    float* bufA; cudaGetSymbolAddress((void**)&bufA, g_bufA);
    float* bufB; cudaGetSymbolAddress((void**)&bufB, g_bufB);
    float* bufC; cudaGetSymbolAddress((void**)&bufC, g_bufC);
    __nv_bfloat16* wt1; cudaGetSymbolAddress((void**)&wt1, g_wt1);
    __nv_bfloat16* wt2; cudaGetSymbolAddress((void**)&wt2, g_wt2);
    __nv_bfloat16* gw1; cudaGetSymbolAddress((void**)&gw1, g_gw1);
    __nv_bfloat16* gw2; cudaGetSymbolAddress((void**)&gw2, g_gw2);
    __nv_bfloat16* ow1; cudaGetSymbolAddress((void**)&ow1, g_ow1);
    __nv_bfloat16* ow2; cudaGetSymbolAddress((void**)&ow2, g_ow2);

    // first kernel launched normally (serial w.r.t. previous graph replay)
    phist_kernel<<<EDGES / 256, 256>>>(dst, reg_w, reg_b, t1_w, t2_w,
                                       gcn1_w, gcn2_w, o1_w, o2_w);
    launchPDL(scan1_kernel, dim3(128), dim3(256), 0);
    launchPDL(scan3_kernel, dim3(NROWS / 256), dim3(256), 0, reg_b, out);
    launchPDL(scatter_kernel, dim3(EDGES / 256), dim3(256), 0, src, dst);

    // -------- layer 1 --------
    launchPDL(gemm_mma_kernel<32>, dim3(NROWS / 128), dim3(256), (size_t)GM_SMEM,
              x, (const __nv_bfloat16*)gw1, bufA);
    launchPDL(gather_agg_kernel, dim3(NROWS / 16), dim3(256), 0,
              (const float*)bufA, gcn1_b, bufB);
    launchPDL(tconv_mma_kernel, dim3(1024), dim3(256), (size_t)TM_SMEM,
              (const float*)bufB, (const __nv_bfloat16*)wt1, t1_b, bufC, 0);
    launchPDL(fused_gemm2_kernel, dim3(1024), dim3(256), (size_t)F2_SMEM,
              (const float*)bufC, (const __nv_bfloat16*)ow1, (const __nv_bfloat16*)gw2,
              o1_b, bn1_g, bn1_b, bufA);

    // -------- layer 2 --------
    launchPDL(gather_agg_kernel, dim3(NROWS / 16), dim3(256), 0,
              (const float*)bufA, gcn2_b, bufB);
    launchPDL(tconv_mma_kernel, dim3(1024), dim3(256), (size_t)TM_SMEM,
              (const float*)bufB, (const __nv_bfloat16*)wt2, t2_b, bufC, 128);
    launchPDL(fused_final_kernel, dim3(NROWS / 128), dim3(256), (size_t)FM_SMEM,
              (const float*)bufC, (const __nv_bfloat16*)ow2, o2_b, bn2_g, bn2_b, out, 128);
}